// round 15
// baseline (speedup 1.0000x reference)
#include <cuda_runtime.h>
#include <cuda_bf16.h>
#include <math.h>
#include <stdint.h>

#define CDIV(a,b) (((a)+(b)-1)/(b))
typedef unsigned long long ull;

constexpr int MAXTOK = 130560;
constexpr int ELEMS  = 4*64*256*128;

constexpr size_t OF_GK  = 0;
constexpr size_t OF_D01 = OF_GK  + (size_t)MAXTOK*256;
constexpr size_t OF_Y4  = OF_D01 + (size_t)MAXTOK*128;
constexpr size_t ARENA_TOTAL = OF_Y4 + (size_t)ELEMS;

__device__ __align__(128) float g_arena[ARENA_TOTAL];
__device__ __align__(128) __nv_bfloat16 g_qvh[(size_t)MAXTOK*1024];
__device__ __align__(128) __nv_bfloat16 g_qvl[(size_t)MAXTOK*1024];
__device__ __align__(128) __nv_bfloat16 g_fh[(size_t)MAXTOK*128];
__device__ __align__(128) __nv_bfloat16 g_fl[(size_t)MAXTOK*128];
__device__ __align__(128) __nv_bfloat16 g_ogh[(size_t)MAXTOK*256];
__device__ __align__(128) __nv_bfloat16 g_ogl[(size_t)MAXTOK*256];
__device__ __align__(128) __nv_bfloat16 g_wcat_h[1280*128];   // wp | wgg
__device__ __align__(128) __nv_bfloat16 g_wcat_l[1280*128];
__device__ __align__(128) __nv_bfloat16 g_wfT_h[128*256];
__device__ __align__(128) __nv_bfloat16 g_wfT_l[128*256];

__device__ __forceinline__ void bsplit(float x, __nv_bfloat16& h, __nv_bfloat16& l) {
    h = __float2bfloat16_rn(x);
    l = __float2bfloat16_rn(x - __bfloat162float(h));
}
__device__ __forceinline__ uint32_t pkbf(float x, float y) {
    uint32_t r; asm("cvt.rn.bf16x2.f32 %0, %1, %2;" : "=r"(r) : "f"(y), "f"(x)); return r;
}
__device__ __forceinline__ void bsplit2(float x0, float x1, uint32_t& hp, uint32_t& lp) {
    hp = pkbf(x0, x1);
    float h0 = __uint_as_float(hp << 16);
    float h1 = __uint_as_float(hp & 0xFFFF0000u);
    lp = pkbf(x0 - h0, x1 - h1);
}
__device__ __forceinline__ float blo(uint32_t u) { return __uint_as_float(u << 16); }
__device__ __forceinline__ float bhi(uint32_t u) { return __uint_as_float(u & 0xFFFF0000u); }

// ---------------------------------------------------------------------------
// Fused weight prep (validated R10)
// ---------------------------------------------------------------------------
__global__ void prep_kernel(const float* __restrict__ Wq, const float* __restrict__ Wk,
                            const float* __restrict__ Wv, const float* __restrict__ Wr,
                            const float* __restrict__ Wg1, const float* __restrict__ Wg2,
                            const float* __restrict__ Wo, const float* __restrict__ ctw,
                            __nv_bfloat16* __restrict__ wch, __nv_bfloat16* __restrict__ wcl,
                            __nv_bfloat16* __restrict__ wfh, __nv_bfloat16* __restrict__ wfl)
{
    const int blk = blockIdx.x;
    if (blk < 512) {
        int idx = blk * 256 + threadIdx.x;
        int n = idx >> 7, k = idx & 127;
        int grp = n >> 8, nn = n & 255;
        const float* W = (grp == 0) ? Wq : (grp == 1) ? Wk : (grp == 2) ? Wv : Wr;
        float x = W[k*256 + nn] * ((grp == 0) ? 0.125f : 1.f);
        __nv_bfloat16 h, l; bsplit(x, h, l);
        wch[idx] = h; wcl[idx] = l;
    } else if (blk < 640) {
        int idx = (blk - 512) * 256 + threadIdx.x;
        int n = idx >> 7, k = idx & 127;
        float s = 0.f;
        #pragma unroll
        for (int j = 0; j < 32; j++) s += __ldg(&Wg1[k*32 + j]) * __ldg(&Wg2[j*256 + n]);
        __nv_bfloat16 h, l; bsplit(s, h, l);
        wch[1024*128 + idx] = h; wcl[1024*128 + idx] = l;
    } else {
        int idx = (blk - 640) * 256 + threadIdx.x;
        int n = idx >> 8, k = idx & 255;
        float s = 0.f;
        #pragma unroll 8
        for (int j = 0; j < 128; j++) s += __ldg(&Wo[k*128 + j]) * __ldg(&ctw[j*128 + n]);
        __nv_bfloat16 h, l; bsplit(s, h, l);
        wfh[idx] = h; wfl[idx] = l;
    }
}

__device__ __forceinline__ uint32_t s2u(const void* p) {
    uint32_t a;
    asm("{ .reg .u64 t; cvta.to.shared.u64 t, %1; cvt.u32.u64 %0, t; }" : "=r"(a) : "l"(p));
    return a;
}
#define SWZ(x) ((x) ^ (((x) >> 3) & 0x70))
__device__ __forceinline__ void ldm4(uint32_t* r, uint32_t addr) {
    asm volatile("ldmatrix.sync.aligned.m8n8.x4.shared.b16 {%0,%1,%2,%3}, [%4];"
        : "=r"(r[0]), "=r"(r[1]), "=r"(r[2]), "=r"(r[3]) : "r"(addr));
}
__device__ __forceinline__ void ldm4t(uint32_t* r, uint32_t addr) {
    asm volatile("ldmatrix.sync.aligned.m8n8.x4.trans.shared.b16 {%0,%1,%2,%3}, [%4];"
        : "=r"(r[0]), "=r"(r[1]), "=r"(r[2]), "=r"(r[3]) : "r"(addr));
}
__device__ __forceinline__ void mma16816(float* d, const uint32_t* a, uint32_t b0, uint32_t b1) {
    asm volatile("mma.sync.aligned.m16n8k16.row.col.f32.bf16.bf16.f32 "
        "{%0,%1,%2,%3}, {%4,%5,%6,%7}, {%8,%9}, {%0,%1,%2,%3};"
        : "+f"(d[0]), "+f"(d[1]), "+f"(d[2]), "+f"(d[3])
        : "r"(a[0]), "r"(a[1]), "r"(a[2]), "r"(a[3]), "r"(b0), "r"(b1));
}
#define CPA16(dst, src) \
    asm volatile("cp.async.cg.shared.global [%0], [%1], 16;" :: "r"(dst), "l"(src))

// ---------------------------------------------------------------------------
// Shared GEMM mainloop (validated)
// ---------------------------------------------------------------------------
struct GemmCtx {
    uint32_t sb; int tid, lane, w, m0w, n0w, lrow, lk8;
};
__device__ __forceinline__ void gemm_main(
    GemmCtx& g, float d[2][8][4],
    const __nv_bfloat16* Ah, const __nv_bfloat16* Al,
    const __nv_bfloat16* Bh, const __nv_bfloat16* Bl,
    int m0, int bn0, int K)
{
    auto issue = [&](int ch, int st) {
        const int kc0 = ch << 6;
        const uint32_t sbase = g.sb + st*65536;
        #pragma unroll
        for (int it = 0; it < 4; it++) {
            int i = g.tid + it*256;
            int r = i >> 3, gg = i & 7;
            uint32_t doff = SWZ(r*128 + gg*16);
            size_t aoff = (size_t)(m0 + r)*K + kc0 + gg*8;
            size_t boff = (size_t)(bn0 + r)*K + kc0 + gg*8;
            CPA16(sbase +         doff, Ah + aoff);
            CPA16(sbase + 16384 + doff, Al + aoff);
            CPA16(sbase + 32768 + doff, Bh + boff);
            CPA16(sbase + 49152 + doff, Bl + boff);
        }
        asm volatile("cp.async.commit_group;" ::: "memory");
    };
    const int nch = K >> 6;
    issue(0, 0);
    for (int ch = 0; ch < nch; ch++) {
        const bool nxt = (ch + 1) < nch;
        if (nxt) issue(ch + 1, (ch + 1) & 1);
        if (nxt) asm volatile("cp.async.wait_group 1;" ::: "memory");
        else     asm volatile("cp.async.wait_group 0;" ::: "memory");
        __syncthreads();
        const uint32_t sbase = g.sb + (ch & 1)*65536;
        #pragma unroll
        for (int ks = 0; ks < 4; ks++) {
            const int kcol = ks*16 + g.lk8;
            uint32_t ah[2][4], al2[2][4], bb[4][4];
            #pragma unroll
            for (int mt = 0; mt < 2; mt++) {
                uint32_t off = SWZ((g.m0w + mt*16 + g.lrow)*128 + kcol*2);
                ldm4(ah[mt],  sbase + off);
                ldm4(al2[mt], sbase + 16384 + off);
            }
            #pragma unroll
            for (int nt2 = 0; nt2 < 4; nt2++) {
                uint32_t off = SWZ((g.n0w + nt2*16 + g.lrow)*128 + kcol*2);
                ldm4(bb[nt2], sbase + 32768 + off);
            }
            #pragma unroll
            for (int mt = 0; mt < 2; mt++)
                #pragma unroll
                for (int nt = 0; nt < 8; nt++) {
                    uint32_t b0 = (nt & 1) ? bb[nt>>1][1] : bb[nt>>1][0];
                    uint32_t b1 = (nt & 1) ? bb[nt>>1][3] : bb[nt>>1][2];
                    mma16816(d[mt][nt], ah[mt],  b0, b1);
                    mma16816(d[mt][nt], al2[mt], b0, b1);
                }
            #pragma unroll
            for (int nt2 = 0; nt2 < 4; nt2++) {
                uint32_t off = SWZ((g.n0w + nt2*16 + g.lrow)*128 + kcol*2);
                ldm4(bb[nt2], sbase + 49152 + off);
            }
            #pragma unroll
            for (int mt = 0; mt < 2; mt++)
                #pragma unroll
                for (int nt = 0; nt < 8; nt++) {
                    uint32_t b0 = (nt & 1) ? bb[nt>>1][1] : bb[nt>>1][0];
                    uint32_t b1 = (nt & 1) ? bb[nt>>1][3] : bb[nt>>1][2];
                    mma16816(d[mt][nt], ah[mt], b0, b1);
                }
        }
        __syncthreads();
    }
}
__device__ __forceinline__ GemmCtx mk_ctx(uint32_t sb) {
    GemmCtx g;
    g.tid = threadIdx.x; g.lane = g.tid & 31; g.w = g.tid >> 5;
    g.m0w = (g.w & 3) * 32; g.n0w = (g.w >> 2) * 64;
    g.lrow = g.lane & 15; g.lk8 = (g.lane >> 4) << 3;
    g.sb = sb;
    return g;
}

// Merged qkvr+gk GEMM. Grid (10, Mt) for A-tile L2 reuse.
// yi<8 -> qkvr emitted as bf16 hi/lo via smem-staged COALESCED epilogue.
// yi>=8 -> gk fp32 (logsig epi).
__global__ void __launch_bounds__(256, 1)
hg2c(const __nv_bfloat16* __restrict__ Ah, const __nv_bfloat16* __restrict__ Al,
     const __nv_bfloat16* __restrict__ Bh, const __nv_bfloat16* __restrict__ Bl,
     __nv_bfloat16* __restrict__ qvh, __nv_bfloat16* __restrict__ qvl,
     float* __restrict__ Cg, int M)
{
    extern __shared__ char smem[];
    GemmCtx g = mk_ctx(s2u(smem));
    const int m0 = blockIdx.y * 128;
    const int yi = blockIdx.x;
    float d[2][8][4];
    #pragma unroll
    for (int mt = 0; mt < 2; mt++)
        #pragma unroll
        for (int nt = 0; nt < 8; nt++)
            #pragma unroll
            for (int u = 0; u < 4; u++) d[mt][nt][u] = 0.f;

    gemm_main(g, d, Ah, Al, Bh, Bl, m0, yi * 128, 128);

    const int er = g.lane >> 2, ec = (g.lane & 3) * 2;
    if (yi >= 8) {
        const int nb = (yi - 8) * 128;
        #pragma unroll
        for (int mt = 0; mt < 2; mt++)
            #pragma unroll
            for (int nt = 0; nt < 8; nt++) {
                float v[4] = {d[mt][nt][0], d[mt][nt][1], d[mt][nt][2], d[mt][nt][3]};
                #pragma unroll
                for (int u = 0; u < 4; u++)
                    v[u] = (fminf(v[u], 0.f) - log1pf(__expf(-fabsf(v[u])))) * (1.f/32.f);
                size_t m = (size_t)(m0 + g.m0w + mt*16 + er);
                int    n = nb + g.n0w + nt*8 + ec;
                *reinterpret_cast<float2*>(&Cg[m*256 + n])       = make_float2(v[0], v[1]);
                *reinterpret_cast<float2*>(&Cg[(m + 8)*256 + n]) = make_float2(v[2], v[3]);
            }
    } else {
        const int nb2 = yi * 64;   // u32 col base
        uint32_t* smU = reinterpret_cast<uint32_t*>(smem);       // [128][65]
        uint32_t* smL = smU + 128*65;
        #pragma unroll
        for (int mt = 0; mt < 2; mt++)
            #pragma unroll
            for (int nt = 0; nt < 8; nt++) {
                int r1 = g.m0w + mt*16 + er;
                int c2 = (g.n0w + nt*8 + ec) >> 1;
                uint32_t hp, lp;
                bsplit2(d[mt][nt][0], d[mt][nt][1], hp, lp);
                smU[r1*65 + c2] = hp; smL[r1*65 + c2] = lp;
                bsplit2(d[mt][nt][2], d[mt][nt][3], hp, lp);
                smU[(r1+8)*65 + c2] = hp; smL[(r1+8)*65 + c2] = lp;
            }
        __syncthreads();
        uint32_t* qh = reinterpret_cast<uint32_t*>(qvh);
        uint32_t* ql = reinterpret_cast<uint32_t*>(qvl);
        #pragma unroll
        for (int it = 0; it < 32; it++) {
            int i = g.tid + it*256;
            int r = i >> 6, c2 = i & 63;
            size_t o = (size_t)(m0 + r)*512 + nb2 + c2;
            qh[o] = smU[r*65 + c2];
            ql[o] = smL[r*65 + c2];
        }
    }
}

// d01 GEMM (og @ wf). trans=0: C[m][n]; trans=1: C[n][m] via smem transpose.
__global__ void __launch_bounds__(256, 1)
hg2(const __nv_bfloat16* __restrict__ Ah, const __nv_bfloat16* __restrict__ Al,
    const __nv_bfloat16* __restrict__ Bh, const __nv_bfloat16* __restrict__ Bl,
    float* __restrict__ C, int M, int N, int K, int trans)
{
    extern __shared__ char smem[];
    GemmCtx g = mk_ctx(s2u(smem));
    const int m0 = blockIdx.x * 128;
    const int n0 = blockIdx.y * 128;
    float d[2][8][4];
    #pragma unroll
    for (int mt = 0; mt < 2; mt++)
        #pragma unroll
        for (int nt = 0; nt < 8; nt++)
            #pragma unroll
            for (int u = 0; u < 4; u++) d[mt][nt][u] = 0.f;

    gemm_main(g, d, Ah, Al, Bh, Bl, m0, n0, K);

    const int er = g.lane >> 2, ec = (g.lane & 3) * 2;
    if (!trans) {
        #pragma unroll
        for (int mt = 0; mt < 2; mt++) {
            #pragma unroll
            for (int nt = 0; nt < 8; nt++) {
                size_t m = (size_t)(m0 + g.m0w + mt*16 + er);
                int    n = n0 + g.n0w + nt*8 + ec;
                *reinterpret_cast<float2*>(&C[m*N + n])       = make_float2(d[mt][nt][0], d[mt][nt][1]);
                *reinterpret_cast<float2*>(&C[(m + 8)*N + n]) = make_float2(d[mt][nt][2], d[mt][nt][3]);
            }
        }
    } else {
        float* sm = reinterpret_cast<float*>(smem);
        #pragma unroll
        for (int mt = 0; mt < 2; mt++) {
            #pragma unroll
            for (int nt = 0; nt < 8; nt++) {
                int r1 = g.m0w + mt*16 + er;
                int cb = g.n0w + nt*8 + ec;
                sm[r1*129 + cb]       = d[mt][nt][0];
                sm[r1*129 + cb + 1]   = d[mt][nt][1];
                sm[(r1+8)*129 + cb]     = d[mt][nt][2];
                sm[(r1+8)*129 + cb + 1] = d[mt][nt][3];
            }
        }
        __syncthreads();
        #pragma unroll
        for (int j = 0; j < 16; j++) {
            int col = g.w + 8*j;
            #pragma unroll
            for (int r = 0; r < 4; r++) {
                int row = g.lane + 32*r;
                C[(size_t)(n0 + col)*M + m0 + row] = sm[row*129 + col];
            }
        }
    }
}

// ---------------------------------------------------------------------------
// Fused LN + unfold (validated R9)
// ---------------------------------------------------------------------------
__global__ void __launch_bounds__(128)
lnf0_kernel(const float* __restrict__ x, const float* __restrict__ gamma,
            const float* __restrict__ beta,
            __nv_bfloat16* __restrict__ fh, __nv_bfloat16* __restrict__ fl)
{
    __shared__ float U[64][129];
    const int tid = threadIdx.x;
    const int b = blockIdx.x >> 8, t = blockIdx.x & 255;
    const int n = blockIdx.x;
    #pragma unroll 8
    for (int c = 0; c < 64; c++)
        U[c][tid] = x[(((size_t)b*64 + c)*256 + t)*128 + tid];
    __syncthreads();
    float sum = 0.f, sq = 0.f;
    #pragma unroll 8
    for (int c = 0; c < 64; c++) { float v = U[c][tid]; sum += v; sq += v*v; }
    float mu  = sum * (1.f/64.f);
    float inv = rsqrtf(sq * (1.f/64.f) - mu*mu + 1e-5f);
    #pragma unroll 8
    for (int c = 0; c < 64; c++)
        U[c][tid] = (U[c][tid] - mu) * inv * gamma[c] + beta[c];
    __syncthreads();
    uint32_t* fhp = reinterpret_cast<uint32_t*>(fh);
    uint32_t* flp = reinterpret_cast<uint32_t*>(fl);
    #pragma unroll 4
    for (int it = 0; it < 64; it++) {
        int idx = it*128 + tid;
        int l = idx >> 6, c = idx & 63;
        if (l >= 127) continue;
        uint32_t hp, lp;
        bsplit2(U[c][l], U[c][l+1], hp, lp);
        size_t o = (size_t)(n*127 + l)*64 + c;
        fhp[o] = hp; flp[o] = lp;
    }
}

__global__ void __launch_bounds__(256)
lnf1_kernel(const float* __restrict__ x, const float* __restrict__ gamma,
            const float* __restrict__ beta,
            __nv_bfloat16* __restrict__ fh, __nv_bfloat16* __restrict__ fl)
{
    extern __shared__ float Us[];
    const int tid = threadIdx.x;
    const int tt = blockIdx.x & 31;
    const int qt = (blockIdx.x >> 5) & 3;
    const int b  = blockIdx.x >> 7;
    const int t0 = tt*8, q0 = qt*32;
    auto UI = [&](int tl, int c, int q) -> float& { return Us[(tl*64 + c)*33 + q]; };

    #pragma unroll
    for (int it = 0; it < 72; it++) {
        int idx = it*256 + tid;
        int q = idx & 31, c = (idx >> 5) & 63, tl = idx >> 11;
        int t = t0 + tl;
        UI(tl, c, q) = (t < 256) ? x[(((size_t)b*64 + c)*256 + t)*128 + q0 + q] : 0.f;
    }
    __syncthreads();
    for (int pair = tid; pair < 288; pair += 256) {
        int tl = pair >> 5, q = pair & 31;
        float sum = 0.f, sq = 0.f;
        #pragma unroll 8
        for (int c = 0; c < 64; c++) { float v = UI(tl, c, q); sum += v; sq += v*v; }
        float mu  = sum * (1.f/64.f);
        float inv = rsqrtf(sq * (1.f/64.f) - mu*mu + 1e-5f);
        #pragma unroll 8
        for (int c = 0; c < 64; c++)
            UI(tl, c, q) = (UI(tl, c, q) - mu) * inv * gamma[c] + beta[c];
    }
    __syncthreads();
    uint32_t* fhp = reinterpret_cast<uint32_t*>(fh);
    uint32_t* flp = reinterpret_cast<uint32_t*>(fl);
    #pragma unroll 4
    for (int it = 0; it < 64; it++) {
        int idx = it*256 + tid;
        int c = idx & 63, tl = (idx >> 6) & 7, q = idx >> 9;
        int l = t0 + tl;
        if (l >= 255) continue;
        uint32_t hp, lp;
        bsplit2(UI(tl, c, q), UI(tl+1, c, q), hp, lp);
        size_t o = ((size_t)(b*128 + q0 + q)*255 + l)*64 + c;
        fhp[o] = hp; flp[o] = lp;
    }
}

// ---------------------------------------------------------------------------
// GLA v7: register S master + shfl cumsum + qkvr read as bf16 hi/lo
// ---------------------------------------------------------------------------
constexpr int G_SH = 0,     G_SL = 8192;
constexpr int G_QH = 16384, G_QL = 20480, G_KH = 24576, G_KL = 28672;
constexpr int G_VH = 32768, G_VL = 36864, G_AH = 40960, G_AL = 45056;
constexpr int G_U  = 49152, G_GL = 57856, GSM = 58112;

__global__ void __launch_bounds__(256, 3)
gla_kernel(const __nv_bfloat16* __restrict__ qvh, const __nv_bfloat16* __restrict__ qvl,
           const float* __restrict__ gkb, const float* __restrict__ gnp,
           __nv_bfloat16* __restrict__ ogh, __nv_bfloat16* __restrict__ ogl,
           int L, int nc, int order, int Nseq)
{
    extern __shared__ char smem[];
    const uint32_t sb = s2u(smem);
    float* Uf  = reinterpret_cast<float*>(smem + G_U);
    float* glf = reinterpret_cast<float*>(smem + G_GL);
    const int n = blockIdx.x >> 2, h = blockIdx.x & 3;
    const int tid = threadIdx.x, lane = tid & 31, w = tid >> 5;
    const uint32_t* qhp = reinterpret_cast<const uint32_t*>(qvh);
    const uint32_t* qlp = reinterpret_cast<const uint32_t*>(qvl);

    float sreg[4][4];
    #pragma unroll
    for (int i = 0; i < 4; i++)
        #pragma unroll
        for (int j = 0; j < 4; j++) sreg[i][j] = 0.f;

    for (int i = tid; i < 16384/4; i += 256) reinterpret_cast<uint32_t*>(smem)[i] = 0u;
    __syncthreads();

    for (int c = 0; c < nc; c++) {
        const int lbase = c * 32;
        #pragma unroll
        for (int r = 0; r < 2; r++) {
            int i = tid + r*256, t = i >> 4, d4 = (i & 15) * 4, l = lbase + t;
            float4 gv = make_float4(0,0,0,0);
            if (l < L)
                gv = *reinterpret_cast<const float4*>(&gkb[((size_t)(n*L + l))*256 + h*64 + d4]);
            *reinterpret_cast<float4*>(&Uf[t*68 + d4]) = gv;
        }
        __syncthreads();
        // warp-shuffle inclusive scan along t: warp w handles columns w*8..w*8+7
        {
            float v[8];
            #pragma unroll
            for (int j = 0; j < 8; j++) v[j] = Uf[lane*68 + w*8 + j];
            #pragma unroll
            for (int off = 1; off < 32; off <<= 1) {
                #pragma unroll
                for (int j = 0; j < 8; j++) {
                    float up = __shfl_up_sync(0xFFFFFFFFu, v[j], off);
                    if (lane >= off) v[j] += up;
                }
            }
            #pragma unroll
            for (int j = 0; j < 8; j++) {
                Uf[lane*68 + w*8 + j] = v[j];
                if (lane == 31) glf[w*8 + j] = v[j];
            }
        }
        __syncthreads();
        #pragma unroll
        for (int r = 0; r < 2; r++) {
            int i = tid + r*256, t = i >> 4, d4 = (i & 15) * 4, l = lbase + t;
            float4 qv = make_float4(0,0,0,0), kv = qv, vv = qv;
            if (l < L) {
                size_t base = (((size_t)(n*L + l))*1024 + h*64 + d4) >> 1;
                uint2 qh2 = *reinterpret_cast<const uint2*>(&qhp[base]);
                uint2 ql2 = *reinterpret_cast<const uint2*>(&qlp[base]);
                uint2 kh2 = *reinterpret_cast<const uint2*>(&qhp[base + 128]);
                uint2 kl2 = *reinterpret_cast<const uint2*>(&qlp[base + 128]);
                uint2 vh2 = *reinterpret_cast<const uint2*>(&qhp[base + 256]);
                uint2 vl2 = *reinterpret_cast<const uint2*>(&qlp[base + 256]);
                qv = make_float4(blo(qh2.x)+blo(ql2.x), bhi(qh2.x)+bhi(ql2.x),
                                 blo(qh2.y)+blo(ql2.y), bhi(qh2.y)+bhi(ql2.y));
                kv = make_float4(blo(kh2.x)+blo(kl2.x), bhi(kh2.x)+bhi(kl2.x),
                                 blo(kh2.y)+blo(kl2.y), bhi(kh2.y)+bhi(kl2.y));
                vv = make_float4(blo(vh2.x)+blo(vl2.x), bhi(vh2.x)+bhi(vl2.x),
                                 blo(vh2.y)+blo(vl2.y), bhi(vh2.y)+bhi(vl2.y));
                float4 g = *reinterpret_cast<const float4*>(&Uf[t*68 + d4]);
                qv.x *= __expf(g.x);  qv.y *= __expf(g.y);
                qv.z *= __expf(g.z);  qv.w *= __expf(g.w);
                kv.x *= __expf(-g.x); kv.y *= __expf(-g.y);
                kv.z *= __expf(-g.z); kv.w *= __expf(-g.w);
            }
            uint32_t off = SWZ(t*128 + d4*2);
            uint32_t h0, l0, h1, l1;
            bsplit2(qv.x, qv.y, h0, l0); bsplit2(qv.z, qv.w, h1, l1);
            *reinterpret_cast<uint2*>(smem + G_QH + off) = make_uint2(h0, h1);
            *reinterpret_cast<uint2*>(smem + G_QL + off) = make_uint2(l0, l1);
            bsplit2(kv.x, kv.y, h0, l0); bsplit2(kv.z, kv.w, h1, l1);
            *reinterpret_cast<uint2*>(smem + G_KH + off) = make_uint2(h0, h1);
            *reinterpret_cast<uint2*>(smem + G_KL + off) = make_uint2(l0, l1);
            bsplit2(vv.x, vv.y, h0, l0); bsplit2(vv.z, vv.w, h1, l1);
            *reinterpret_cast<uint2*>(smem + G_VH + off) = make_uint2(h0, h1);
            *reinterpret_cast<uint2*>(smem + G_VL + off) = make_uint2(l0, l1);
        }
        __syncthreads();
        // A = QK^T masked
        {
            const int mrow = 16*(w & 1) + (lane & 15);
            const int s0   = 8*(w >> 1);
            uint32_t kbh[2][4], kbl[2][4];
            #pragma unroll
            for (int g = 0; g < 2; g++) {
                uint32_t off = SWZ((s0 + (lane & 7))*128 + (g*32 + (lane >> 3)*8)*2);
                ldm4(kbh[g], sb + G_KH + off);
                ldm4(kbl[g], sb + G_KL + off);
            }
            float dA[4] = {0,0,0,0};
            #pragma unroll
            for (int ks = 0; ks < 4; ks++) {
                uint32_t ah[4], al[4];
                uint32_t aoff = SWZ(mrow*128 + (ks*16 + (lane >> 4)*8)*2);
                ldm4(ah, sb + G_QH + aoff);
                ldm4(al, sb + G_QL + aoff);
                uint32_t b0h = kbh[ks>>1][(ks&1)*2], b1h = kbh[ks>>1][(ks&1)*2+1];
                uint32_t b0l = kbl[ks>>1][(ks&1)*2], b1l = kbl[ks>>1][(ks&1)*2+1];
                mma16816(dA, ah, b0h, b1h);
                mma16816(dA, ah, b0l, b1l);
                mma16816(dA, al, b0h, b1h);
            }
            int r0 = 16*(w & 1) + (lane >> 2);
            int cc = s0 + 2*(lane & 3);
            float v00 = (cc   <= r0  ) ? dA[0] : 0.f;
            float v01 = (cc+1 <= r0  ) ? dA[1] : 0.f;
            float v10 = (cc   <= r0+8) ? dA[2] : 0.f;
            float v11 = (cc+1 <= r0+8) ? dA[3] : 0.f;
            uint32_t hp, lp;
            bsplit2(v00, v01, hp, lp);
            *reinterpret_cast<uint32_t*>(smem + G_AH + SWZ(r0*128 + cc*2)) = hp;
            *reinterpret_cast<uint32_t*>(smem + G_AL + SWZ(r0*128 + cc*2)) = lp;
            bsplit2(v10, v11, hp, lp);
            *reinterpret_cast<uint32_t*>(smem + G_AH + SWZ((r0+8)*128 + cc*2)) = hp;
            *reinterpret_cast<uint32_t*>(smem + G_AL + SWZ((r0+8)*128 + cc*2)) = lp;
        }
        __syncthreads();
        // o = A@V + Q@S(old) -> U
        {
            const int mrow = 16*(w & 1) + (lane & 15);
            const int nv0  = 16*(w >> 1);
            float d0[4] = {0,0,0,0}, d1[4] = {0,0,0,0};
            #pragma unroll
            for (int ks = 0; ks < 2; ks++) {
                uint32_t ah[4], al[4], vh[4], vl[4];
                uint32_t aoff = SWZ(mrow*128 + (ks*16 + (lane >> 4)*8)*2);
                ldm4(ah, sb + G_AH + aoff);
                ldm4(al, sb + G_AL + aoff);
                uint32_t boff = SWZ((ks*16 + ((lane >> 3) & 1)*8 + (lane & 7))*128
                                    + (nv0 + (lane >> 4)*8)*2);
                ldm4t(vh, sb + G_VH + boff);
                ldm4t(vl, sb + G_VL + boff);
                mma16816(d0, ah, vh[0], vh[1]);
                mma16816(d0, ah, vl[0], vl[1]);
                mma16816(d0, al, vh[0], vh[1]);
                mma16816(d1, ah, vh[2], vh[3]);
                mma16816(d1, ah, vl[2], vl[3]);
                mma16816(d1, al, vh[2], vh[3]);
            }
            #pragma unroll
            for (int ks = 0; ks < 4; ks++) {
                uint32_t qh[4], ql[4], sh[4], sl[4];
                uint32_t aoff = SWZ(mrow*128 + (ks*16 + (lane >> 4)*8)*2);
                ldm4(qh, sb + G_QH + aoff);
                ldm4(ql, sb + G_QL + aoff);
                uint32_t boff = SWZ((ks*16 + ((lane >> 3) & 1)*8 + (lane & 7))*128
                                    + (nv0 + (lane >> 4)*8)*2);
                ldm4t(sh, sb + G_SH + boff);
                ldm4t(sl, sb + G_SL + boff);
                mma16816(d0, qh, sh[0], sh[1]);
                mma16816(d0, qh, sl[0], sl[1]);
                mma16816(d0, ql, sh[0], sh[1]);
                mma16816(d1, qh, sh[2], sh[3]);
                mma16816(d1, qh, sl[2], sl[3]);
                mma16816(d1, ql, sh[2], sh[3]);
            }
            int r0 = 16*(w & 1) + (lane >> 2);
            int c0 = nv0 + 2*(lane & 3);
            *reinterpret_cast<float2*>(&Uf[r0*68 + c0])         = make_float2(d0[0], d0[1]);
            *reinterpret_cast<float2*>(&Uf[(r0+8)*68 + c0])     = make_float2(d0[2], d0[3]);
            *reinterpret_cast<float2*>(&Uf[r0*68 + c0 + 8])     = make_float2(d1[0], d1[1]);
            *reinterpret_cast<float2*>(&Uf[(r0+8)*68 + c0 + 8]) = make_float2(d1[2], d1[3]);
        }
        __syncthreads();
        // gate epilogue -> og hi/lo
        {
            int t = tid >> 3, dv0 = (tid & 7) * 8;
            float4 oa = *reinterpret_cast<const float4*>(&Uf[t*68 + dv0]);
            float4 obv = *reinterpret_cast<const float4*>(&Uf[t*68 + dv0 + 4]);
            float o8[8] = {oa.x,oa.y,oa.z,oa.w,obv.x,obv.y,obv.z,obv.w};
            float ss = 0.f;
            #pragma unroll
            for (int j = 0; j < 8; j++) ss += o8[j]*o8[j];
            ss += __shfl_xor_sync(0xFFFFFFFFu, ss, 4, 8);
            ss += __shfl_xor_sync(0xFFFFFFFFu, ss, 2, 8);
            ss += __shfl_xor_sync(0xFFFFFFFFu, ss, 1, 8);
            float inv = rsqrtf(ss * (1.f/64.f) + 1e-5f);
            int l = lbase + t;
            if (l < L) {
                size_t rb = (((size_t)(n*L + l))*1024 + 768 + h*64 + dv0) >> 1;
                uint4 rh4 = *reinterpret_cast<const uint4*>(&qhp[rb]);
                uint4 rl4 = *reinterpret_cast<const uint4*>(&qlp[rb]);
                float rr[8] = {
                    blo(rh4.x)+blo(rl4.x), bhi(rh4.x)+bhi(rl4.x),
                    blo(rh4.y)+blo(rl4.y), bhi(rh4.y)+bhi(rl4.y),
                    blo(rh4.z)+blo(rl4.z), bhi(rh4.z)+bhi(rl4.z),
                    blo(rh4.w)+blo(rl4.w), bhi(rh4.w)+bhi(rl4.w)};
                float4 g0 = *reinterpret_cast<const float4*>(&gnp[h*64 + dv0]);
                float4 g1 = *reinterpret_cast<const float4*>(&gnp[h*64 + dv0 + 4]);
                float gg[8] = {g0.x,g0.y,g0.z,g0.w,g1.x,g1.y,g1.z,g1.w};
                float res[8];
                #pragma unroll
                for (int j = 0; j < 8; j++)
                    res[j] = o8[j] * inv * gg[j] * (rr[j] / (1.f + __expf(-rr[j])));
                uint32_t hq[4], lq[4];
                #pragma unroll
                for (int j = 0; j < 4; j++) bsplit2(res[2*j], res[2*j+1], hq[j], lq[j]);
                size_t tok = order ? ((size_t)l*Nseq + n) : ((size_t)n*L + l);
                size_t o = (tok*256 + h*64 + dv0) >> 1;
                *reinterpret_cast<uint4*>(reinterpret_cast<uint32_t*>(ogh) + o)
                    = make_uint4(hq[0], hq[1], hq[2], hq[3]);
                *reinterpret_cast<uint4*>(reinterpret_cast<uint32_t*>(ogl) + o)
                    = make_uint4(lq[0], lq[1], lq[2], lq[3]);
            }
        }
        // S update (register master)
        {
            const int mk0 = 16*(w & 3);
            const int nb  = 32*(w >> 2);
            float dd[4][4];
            #pragma unroll
            for (int i = 0; i < 4; i++)
                #pragma unroll
                for (int j = 0; j < 4; j++) dd[i][j] = 0.f;
            #pragma unroll
            for (int ks = 0; ks < 2; ks++) {
                uint32_t kh[4], kl[4];
                uint32_t aoff = SWZ((ks*16 + ((lane >> 3) >> 1)*8 + (lane & 7))*128
                                    + (mk0 + ((lane >> 3) & 1)*8)*2);
                ldm4t(kh, sb + G_KH + aoff);
                ldm4t(kl, sb + G_KL + aoff);
                #pragma unroll
                for (int np = 0; np < 2; np++) {
                    uint32_t vh[4], vl[4];
                    uint32_t boff = SWZ((ks*16 + ((lane >> 3) & 1)*8 + (lane & 7))*128
                                        + (nb + 16*np + (lane >> 4)*8)*2);
                    ldm4t(vh, sb + G_VH + boff);
                    ldm4t(vl, sb + G_VL + boff);
                    mma16816(dd[np*2],   kh, vh[0], vh[1]);
                    mma16816(dd[np*2],   kh, vl[0], vl[1]);
                    mma16816(dd[np*2],   kl, vh[0], vh[1]);
                    mma16816(dd[np*2+1], kh, vh[2], vh[3]);
                    mma16816(dd[np*2+1], kh, vl[2], vl[3]);
                    mma16816(dd[np*2+1], kl, vh[2], vh[3]);
                }
            }
            int r0 = mk0 + (lane >> 2);
            float e0 = __expf(glf[r0]);
            float e1 = __expf(glf[r0 + 8]);
            #pragma unroll
            for (int tile = 0; tile < 4; tile++) {
                int cc = nb + ((tile >> 1) * 16) + ((tile & 1) * 8) + 2*(lane & 3);
                float s00 = e0*(sreg[tile][0] + dd[tile][0]);
                float s01 = e0*(sreg[tile][1] + dd[tile][1]);
                float s10 = e1*(sreg[tile][2] + dd[tile][2]);
                float s11 = e1*(sreg[tile][3] + dd[tile][3]);
                sreg[tile][0] = s00; sreg[tile][1] = s01;
                sreg[tile][2] = s10; sreg[tile][3] = s11;
                uint32_t hp, lp;
                bsplit2(s00, s01, hp, lp);
                *reinterpret_cast<uint32_t*>(smem + G_SH + SWZ(r0*128 + cc*2)) = hp;
                *reinterpret_cast<uint32_t*>(smem + G_SL + SWZ(r0*128 + cc*2)) = lp;
                bsplit2(s10, s11, hp, lp);
                *reinterpret_cast<uint32_t*>(smem + G_SH + SWZ((r0+8)*128 + cc*2)) = hp;
                *reinterpret_cast<uint32_t*>(smem + G_SL + SWZ((r0+8)*128 + cc*2)) = lp;
            }
        }
        __syncthreads();
    }
}

// ---------------------------------------------------------------------------
// combine kernels (validated R12)
// ---------------------------------------------------------------------------
__global__ void __launch_bounds__(256)
combine0_kernel(const float* __restrict__ d01, const float* __restrict__ ctb,
                const float* __restrict__ resid, float* __restrict__ out)
{
    extern __shared__ float sm[];
    const int tid = threadIdx.x;
    const int n = blockIdx.x;
    const int b = n >> 8, t = n & 255;
    for (int i = tid; i < 127*128; i += 256) {
        int tok = i >> 7, col = i & 127;
        sm[tok*129 + col] = d01[((size_t)n*127 + tok)*128 + col];
    }
    __syncthreads();
    #pragma unroll 4
    for (int i = tid; i < 8192; i += 256) {
        int q = i & 127, c = i >> 7;
        size_t oidx = (((size_t)b*64 + c)*256 + t)*128 + q;
        float acc = resid[oidx] + ctb[c];
        if (q < 127) acc += sm[q*129 + 2*c];
        if (q >= 1)  acc += sm[(q-1)*129 + 2*c + 1];
        out[oidx] = acc;
    }
}

__global__ void combine1_kernel(const float* __restrict__ d01T, const float* __restrict__ ctb,
                                const float* __restrict__ resid, float* __restrict__ out)
{
    int idx = blockIdx.x * blockDim.x + threadIdx.x;
    if (idx >= ELEMS) return;
    int q = idx & 127, t = (idx >> 7) & 255, c = (idx >> 15) & 63, b = idx >> 21;
    float acc = resid[idx] + ctb[c];
    int mcur = t*512 + b*128 + q;
    if (t < 255) acc += d01T[(size_t)(2*c)*MAXTOK + mcur];
    if (t >= 1)  acc += d01T[(size_t)(2*c + 1)*MAXTOK + mcur - 512];
    out[idx] = acc;
}

struct WPtrs {
    __nv_bfloat16 *wch, *wcl, *wfT_h, *wfT_l, *fh, *fl, *ogh, *ogl, *qvh, *qvl;
};
constexpr int HSM2  = 131072;
constexpr int LN1SM = 9*64*33*4;
constexpr int C0SM  = 127*129*4;

static void run_pass(const float* input, const float* gamma, const float* beta,
                     const float* Wq, const float* Wk, const float* Wv,
                     const float* Wg1, const float* Wg2, const float* Wr,
                     const float* gn, const float* Wo,
                     const float* ctw, const float* ctb,
                     const float* resid, float* out,
                     float* A, const WPtrs& W, int pass)
{
    const int N   = pass == 0 ? 1024 : 512;
    const int L   = pass == 0 ? 127  : 255;
    const int nc  = pass == 0 ? 4    : 8;
    const int tok = N * L;
    const int Mt  = tok / 128;

    float* gk  = A + OF_GK;
    float* d01 = A + OF_D01;

    prep_kernel<<<768, 256>>>(Wq, Wk, Wv, Wr, Wg1, Wg2, Wo, ctw,
                              W.wch, W.wcl, W.wfT_h, W.wfT_l);
    if (pass == 0) lnf0_kernel<<<1024, 128>>>(input, gamma, beta, W.fh, W.fl);
    else           lnf1_kernel<<<512, 256, LN1SM>>>(input, gamma, beta, W.fh, W.fl);
    hg2c<<<dim3(10, Mt), 256, HSM2>>>(W.fh, W.fl, W.wch, W.wcl, W.qvh, W.qvl, gk, tok);
    gla_kernel<<<N*4, 256, GSM>>>(W.qvh, W.qvl, gk, gn, W.ogh, W.ogl, L, nc, pass, N);
    hg2<<<dim3(Mt, 1), 256, HSM2>>>(W.ogh, W.ogl, W.wfT_h, W.wfT_l, d01, tok, 128, 256, pass);
    if (pass == 0) combine0_kernel<<<1024, 256, C0SM>>>(d01, ctb, resid, out);
    else           combine1_kernel<<<CDIV(ELEMS, 256), 256>>>(d01, ctb, resid, out);
}

extern "C" void kernel_launch(void* const* d_in, const int* in_sizes, int n_in,
                              void* d_out, int out_size)
{
    const float* x = (const float*)d_in[0];
    auto P = [&](int i) { return (const float*)d_in[i]; };

    float* arena = nullptr;
    cudaGetSymbolAddress((void**)&arena, g_arena);
    float* y4 = arena + OF_Y4;

    WPtrs W;
    cudaGetSymbolAddress((void**)&W.wch,   g_wcat_h);
    cudaGetSymbolAddress((void**)&W.wcl,   g_wcat_l);
    cudaGetSymbolAddress((void**)&W.wfT_h, g_wfT_h);
    cudaGetSymbolAddress((void**)&W.wfT_l, g_wfT_l);
    cudaGetSymbolAddress((void**)&W.fh,    g_fh);
    cudaGetSymbolAddress((void**)&W.fl,    g_fl);
    cudaGetSymbolAddress((void**)&W.ogh,   g_ogh);
    cudaGetSymbolAddress((void**)&W.ogl,   g_ogl);
    cudaGetSymbolAddress((void**)&W.qvh,   g_qvh);
    cudaGetSymbolAddress((void**)&W.qvl,   g_qvl);

    cudaFuncSetAttribute(hg2c, cudaFuncAttributeMaxDynamicSharedMemorySize, HSM2);
    cudaFuncSetAttribute(hg2,  cudaFuncAttributeMaxDynamicSharedMemorySize, HSM2);
    cudaFuncSetAttribute(gla_kernel,  cudaFuncAttributeMaxDynamicSharedMemorySize, GSM);
    cudaFuncSetAttribute(lnf1_kernel, cudaFuncAttributeMaxDynamicSharedMemorySize, LN1SM);
    cudaFuncSetAttribute(combine0_kernel, cudaFuncAttributeMaxDynamicSharedMemorySize, C0SM);

    run_pass(x, P(2), P(3), P(4), P(5), P(6), P(7), P(8), P(9), P(10), P(11), P(12), P(13),
             x, y4, arena, W, 0);
    run_pass(y4, P(14), P(15), P(16), P(17), P(18), P(19), P(20), P(21), P(22), P(23), P(24), P(25),
             y4, (float*)d_out, arena, W, 1);
}

// round 16
// speedup vs baseline: 1.0891x; 1.0891x over previous
#include <cuda_runtime.h>
#include <cuda_bf16.h>
#include <math.h>
#include <stdint.h>

#define CDIV(a,b) (((a)+(b)-1)/(b))
typedef unsigned long long ull;

constexpr int MAXTOK = 130560;
constexpr int ELEMS  = 4*64*256*128;

constexpr size_t OF_QKVR = 0;
constexpr size_t OF_GK   = OF_QKVR + (size_t)MAXTOK*1024;
constexpr size_t OF_D01  = OF_GK   + (size_t)MAXTOK*256;
constexpr size_t OF_Y4   = OF_D01  + (size_t)MAXTOK*128;
constexpr size_t ARENA_TOTAL = OF_Y4 + (size_t)ELEMS;

__device__ __align__(128) float g_arena[ARENA_TOTAL];
__device__ __align__(128) __nv_bfloat16 g_fh[(size_t)MAXTOK*128];
__device__ __align__(128) __nv_bfloat16 g_fl[(size_t)MAXTOK*128];
__device__ __align__(128) __nv_bfloat16 g_ogh[(size_t)MAXTOK*256];
__device__ __align__(128) __nv_bfloat16 g_ogl[(size_t)MAXTOK*256];
// per-pass weight buffers (prep for both passes launched upfront)
__device__ __align__(128) __nv_bfloat16 g_wcat_h[2][1280*128];
__device__ __align__(128) __nv_bfloat16 g_wcat_l[2][1280*128];
__device__ __align__(128) __nv_bfloat16 g_wfT_h[2][128*256];
__device__ __align__(128) __nv_bfloat16 g_wfT_l[2][128*256];

__device__ __forceinline__ void bsplit(float x, __nv_bfloat16& h, __nv_bfloat16& l) {
    h = __float2bfloat16_rn(x);
    l = __float2bfloat16_rn(x - __bfloat162float(h));
}
__device__ __forceinline__ uint32_t pkbf(float x, float y) {
    uint32_t r; asm("cvt.rn.bf16x2.f32 %0, %1, %2;" : "=r"(r) : "f"(y), "f"(x)); return r;
}
__device__ __forceinline__ void bsplit2(float x0, float x1, uint32_t& hp, uint32_t& lp) {
    hp = pkbf(x0, x1);
    float h0 = __uint_as_float(hp << 16);
    float h1 = __uint_as_float(hp & 0xFFFF0000u);
    lp = pkbf(x0 - h0, x1 - h1);
}

// ---------------------------------------------------------------------------
// Fused weight prep (validated R10)
// ---------------------------------------------------------------------------
__global__ void prep_kernel(const float* __restrict__ Wq, const float* __restrict__ Wk,
                            const float* __restrict__ Wv, const float* __restrict__ Wr,
                            const float* __restrict__ Wg1, const float* __restrict__ Wg2,
                            const float* __restrict__ Wo, const float* __restrict__ ctw,
                            __nv_bfloat16* __restrict__ wch, __nv_bfloat16* __restrict__ wcl,
                            __nv_bfloat16* __restrict__ wfh, __nv_bfloat16* __restrict__ wfl)
{
    const int blk = blockIdx.x;
    if (blk < 512) {
        int idx = blk * 256 + threadIdx.x;
        int n = idx >> 7, k = idx & 127;
        int grp = n >> 8, nn = n & 255;
        const float* W = (grp == 0) ? Wq : (grp == 1) ? Wk : (grp == 2) ? Wv : Wr;
        float x = W[k*256 + nn] * ((grp == 0) ? 0.125f : 1.f);
        __nv_bfloat16 h, l; bsplit(x, h, l);
        wch[idx] = h; wcl[idx] = l;
    } else if (blk < 640) {
        int idx = (blk - 512) * 256 + threadIdx.x;
        int n = idx >> 7, k = idx & 127;
        float s = 0.f;
        #pragma unroll
        for (int j = 0; j < 32; j++) s += __ldg(&Wg1[k*32 + j]) * __ldg(&Wg2[j*256 + n]);
        __nv_bfloat16 h, l; bsplit(s, h, l);
        wch[1024*128 + idx] = h; wcl[1024*128 + idx] = l;
    } else {
        int idx = (blk - 640) * 256 + threadIdx.x;
        int n = idx >> 8, k = idx & 255;
        float s = 0.f;
        #pragma unroll 8
        for (int j = 0; j < 128; j++) s += __ldg(&Wo[k*128 + j]) * __ldg(&ctw[j*128 + n]);
        __nv_bfloat16 h, l; bsplit(s, h, l);
        wfh[idx] = h; wfl[idx] = l;
    }
}

__device__ __forceinline__ uint32_t s2u(const void* p) {
    uint32_t a;
    asm("{ .reg .u64 t; cvta.to.shared.u64 t, %1; cvt.u32.u64 %0, t; }" : "=r"(a) : "l"(p));
    return a;
}
#define SWZ(x) ((x) ^ (((x) >> 3) & 0x70))
__device__ __forceinline__ void ldm4(uint32_t* r, uint32_t addr) {
    asm volatile("ldmatrix.sync.aligned.m8n8.x4.shared.b16 {%0,%1,%2,%3}, [%4];"
        : "=r"(r[0]), "=r"(r[1]), "=r"(r[2]), "=r"(r[3]) : "r"(addr));
}
__device__ __forceinline__ void ldm4t(uint32_t* r, uint32_t addr) {
    asm volatile("ldmatrix.sync.aligned.m8n8.x4.trans.shared.b16 {%0,%1,%2,%3}, [%4];"
        : "=r"(r[0]), "=r"(r[1]), "=r"(r[2]), "=r"(r[3]) : "r"(addr));
}
__device__ __forceinline__ void mma16816(float* d, const uint32_t* a, uint32_t b0, uint32_t b1) {
    asm volatile("mma.sync.aligned.m16n8k16.row.col.f32.bf16.bf16.f32 "
        "{%0,%1,%2,%3}, {%4,%5,%6,%7}, {%8,%9}, {%0,%1,%2,%3};"
        : "+f"(d[0]), "+f"(d[1]), "+f"(d[2]), "+f"(d[3])
        : "r"(a[0]), "r"(a[1]), "r"(a[2]), "r"(a[3]), "r"(b0), "r"(b1));
}
#define CPA16(dst, src) \
    asm volatile("cp.async.cg.shared.global [%0], [%1], 16;" :: "r"(dst), "l"(src))

// ---------------------------------------------------------------------------
// Shared GEMM mainloop (validated)
// ---------------------------------------------------------------------------
struct GemmCtx {
    uint32_t sb; int tid, lane, w, m0w, n0w, lrow, lk8;
};
__device__ __forceinline__ void gemm_main(
    GemmCtx& g, float d[2][8][4],
    const __nv_bfloat16* Ah, const __nv_bfloat16* Al,
    const __nv_bfloat16* Bh, const __nv_bfloat16* Bl,
    int m0, int bn0, int K)
{
    auto issue = [&](int ch, int st) {
        const int kc0 = ch << 6;
        const uint32_t sbase = g.sb + st*65536;
        #pragma unroll
        for (int it = 0; it < 4; it++) {
            int i = g.tid + it*256;
            int r = i >> 3, gg = i & 7;
            uint32_t doff = SWZ(r*128 + gg*16);
            size_t aoff = (size_t)(m0 + r)*K + kc0 + gg*8;
            size_t boff = (size_t)(bn0 + r)*K + kc0 + gg*8;
            CPA16(sbase +         doff, Ah + aoff);
            CPA16(sbase + 16384 + doff, Al + aoff);
            CPA16(sbase + 32768 + doff, Bh + boff);
            CPA16(sbase + 49152 + doff, Bl + boff);
        }
        asm volatile("cp.async.commit_group;" ::: "memory");
    };
    const int nch = K >> 6;
    issue(0, 0);
    for (int ch = 0; ch < nch; ch++) {
        const bool nxt = (ch + 1) < nch;
        if (nxt) issue(ch + 1, (ch + 1) & 1);
        if (nxt) asm volatile("cp.async.wait_group 1;" ::: "memory");
        else     asm volatile("cp.async.wait_group 0;" ::: "memory");
        __syncthreads();
        const uint32_t sbase = g.sb + (ch & 1)*65536;
        #pragma unroll
        for (int ks = 0; ks < 4; ks++) {
            const int kcol = ks*16 + g.lk8;
            uint32_t ah[2][4], al2[2][4], bb[4][4];
            #pragma unroll
            for (int mt = 0; mt < 2; mt++) {
                uint32_t off = SWZ((g.m0w + mt*16 + g.lrow)*128 + kcol*2);
                ldm4(ah[mt],  sbase + off);
                ldm4(al2[mt], sbase + 16384 + off);
            }
            #pragma unroll
            for (int nt2 = 0; nt2 < 4; nt2++) {
                uint32_t off = SWZ((g.n0w + nt2*16 + g.lrow)*128 + kcol*2);
                ldm4(bb[nt2], sbase + 32768 + off);
            }
            #pragma unroll
            for (int mt = 0; mt < 2; mt++)
                #pragma unroll
                for (int nt = 0; nt < 8; nt++) {
                    uint32_t b0 = (nt & 1) ? bb[nt>>1][1] : bb[nt>>1][0];
                    uint32_t b1 = (nt & 1) ? bb[nt>>1][3] : bb[nt>>1][2];
                    mma16816(d[mt][nt], ah[mt],  b0, b1);
                    mma16816(d[mt][nt], al2[mt], b0, b1);
                }
            #pragma unroll
            for (int nt2 = 0; nt2 < 4; nt2++) {
                uint32_t off = SWZ((g.n0w + nt2*16 + g.lrow)*128 + kcol*2);
                ldm4(bb[nt2], sbase + 49152 + off);
            }
            #pragma unroll
            for (int mt = 0; mt < 2; mt++)
                #pragma unroll
                for (int nt = 0; nt < 8; nt++) {
                    uint32_t b0 = (nt & 1) ? bb[nt>>1][1] : bb[nt>>1][0];
                    uint32_t b1 = (nt & 1) ? bb[nt>>1][3] : bb[nt>>1][2];
                    mma16816(d[mt][nt], ah[mt], b0, b1);
                }
        }
        __syncthreads();
    }
}
__device__ __forceinline__ GemmCtx mk_ctx(uint32_t sb) {
    GemmCtx g;
    g.tid = threadIdx.x; g.lane = g.tid & 31; g.w = g.tid >> 5;
    g.m0w = (g.w & 3) * 32; g.n0w = (g.w >> 2) * 64;
    g.lrow = g.lane & 15; g.lk8 = (g.lane >> 4) << 3;
    g.sb = sb;
    return g;
}

// Merged qkvr+gk GEMM. Grid (10, Mt) for A-tile L2 reuse.
__global__ void __launch_bounds__(256, 1)
hg2c(const __nv_bfloat16* __restrict__ Ah, const __nv_bfloat16* __restrict__ Al,
     const __nv_bfloat16* __restrict__ Bh, const __nv_bfloat16* __restrict__ Bl,
     float* __restrict__ Cq, float* __restrict__ Cg, int M)
{
    extern __shared__ char smem[];
    GemmCtx g = mk_ctx(s2u(smem));
    const int m0 = blockIdx.y * 128;
    const int yi = blockIdx.x;
    float d[2][8][4];
    #pragma unroll
    for (int mt = 0; mt < 2; mt++)
        #pragma unroll
        for (int nt = 0; nt < 8; nt++)
            #pragma unroll
            for (int u = 0; u < 4; u++) d[mt][nt][u] = 0.f;

    gemm_main(g, d, Ah, Al, Bh, Bl, m0, yi * 128, 128);

    const bool isgk = yi >= 8;
    float* C   = isgk ? Cg : Cq;
    const int Nn = isgk ? 256 : 1024;
    const int nb = (isgk ? (yi - 8) : yi) * 128;
    const int er = g.lane >> 2, ec = (g.lane & 3) * 2;
    #pragma unroll
    for (int mt = 0; mt < 2; mt++) {
        #pragma unroll
        for (int nt = 0; nt < 8; nt++) {
            float v[4] = {d[mt][nt][0], d[mt][nt][1], d[mt][nt][2], d[mt][nt][3]};
            if (isgk) {
                #pragma unroll
                for (int u = 0; u < 4; u++)
                    v[u] = (fminf(v[u], 0.f) - log1pf(__expf(-fabsf(v[u])))) * (1.f/32.f);
            }
            size_t m = (size_t)(m0 + g.m0w + mt*16 + er);
            int    n = nb + g.n0w + nt*8 + ec;
            *reinterpret_cast<float2*>(&C[m*Nn + n])       = make_float2(v[0], v[1]);
            *reinterpret_cast<float2*>(&C[(m + 8)*Nn + n]) = make_float2(v[2], v[3]);
        }
    }
}

// d01 GEMM (og @ wf). trans=0: C[m][n]; trans=1: C[n][m] via smem transpose.
__global__ void __launch_bounds__(256, 1)
hg2(const __nv_bfloat16* __restrict__ Ah, const __nv_bfloat16* __restrict__ Al,
    const __nv_bfloat16* __restrict__ Bh, const __nv_bfloat16* __restrict__ Bl,
    float* __restrict__ C, int M, int N, int K, int trans)
{
    extern __shared__ char smem[];
    GemmCtx g = mk_ctx(s2u(smem));
    const int m0 = blockIdx.x * 128;
    const int n0 = blockIdx.y * 128;
    float d[2][8][4];
    #pragma unroll
    for (int mt = 0; mt < 2; mt++)
        #pragma unroll
        for (int nt = 0; nt < 8; nt++)
            #pragma unroll
            for (int u = 0; u < 4; u++) d[mt][nt][u] = 0.f;

    gemm_main(g, d, Ah, Al, Bh, Bl, m0, n0, K);

    const int er = g.lane >> 2, ec = (g.lane & 3) * 2;
    if (!trans) {
        #pragma unroll
        for (int mt = 0; mt < 2; mt++) {
            #pragma unroll
            for (int nt = 0; nt < 8; nt++) {
                size_t m = (size_t)(m0 + g.m0w + mt*16 + er);
                int    n = n0 + g.n0w + nt*8 + ec;
                *reinterpret_cast<float2*>(&C[m*N + n])       = make_float2(d[mt][nt][0], d[mt][nt][1]);
                *reinterpret_cast<float2*>(&C[(m + 8)*N + n]) = make_float2(d[mt][nt][2], d[mt][nt][3]);
            }
        }
    } else {
        float* sm = reinterpret_cast<float*>(smem);
        #pragma unroll
        for (int mt = 0; mt < 2; mt++) {
            #pragma unroll
            for (int nt = 0; nt < 8; nt++) {
                int r1 = g.m0w + mt*16 + er;
                int cb = g.n0w + nt*8 + ec;
                sm[r1*129 + cb]       = d[mt][nt][0];
                sm[r1*129 + cb + 1]   = d[mt][nt][1];
                sm[(r1+8)*129 + cb]     = d[mt][nt][2];
                sm[(r1+8)*129 + cb + 1] = d[mt][nt][3];
            }
        }
        __syncthreads();
        #pragma unroll
        for (int j = 0; j < 16; j++) {
            int col = g.w + 8*j;
            #pragma unroll
            for (int r = 0; r < 4; r++) {
                int row = g.lane + 32*r;
                C[(size_t)(n0 + col)*M + m0 + row] = sm[row*129 + col];
            }
        }
    }
}

// ---------------------------------------------------------------------------
// Fused LN + unfold (validated R9)
// ---------------------------------------------------------------------------
__global__ void __launch_bounds__(128)
lnf0_kernel(const float* __restrict__ x, const float* __restrict__ gamma,
            const float* __restrict__ beta,
            __nv_bfloat16* __restrict__ fh, __nv_bfloat16* __restrict__ fl)
{
    __shared__ float U[64][129];
    const int tid = threadIdx.x;
    const int b = blockIdx.x >> 8, t = blockIdx.x & 255;
    const int n = blockIdx.x;
    #pragma unroll 8
    for (int c = 0; c < 64; c++)
        U[c][tid] = x[(((size_t)b*64 + c)*256 + t)*128 + tid];
    __syncthreads();
    float sum = 0.f, sq = 0.f;
    #pragma unroll 8
    for (int c = 0; c < 64; c++) { float v = U[c][tid]; sum += v; sq += v*v; }
    float mu  = sum * (1.f/64.f);
    float inv = rsqrtf(sq * (1.f/64.f) - mu*mu + 1e-5f);
    #pragma unroll 8
    for (int c = 0; c < 64; c++)
        U[c][tid] = (U[c][tid] - mu) * inv * gamma[c] + beta[c];
    __syncthreads();
    uint32_t* fhp = reinterpret_cast<uint32_t*>(fh);
    uint32_t* flp = reinterpret_cast<uint32_t*>(fl);
    #pragma unroll 4
    for (int it = 0; it < 64; it++) {
        int idx = it*128 + tid;
        int l = idx >> 6, c = idx & 63;
        if (l >= 127) continue;
        uint32_t hp, lp;
        bsplit2(U[c][l], U[c][l+1], hp, lp);
        size_t o = (size_t)(n*127 + l)*64 + c;
        fhp[o] = hp; flp[o] = lp;
    }
}

__global__ void __launch_bounds__(256)
lnf1_kernel(const float* __restrict__ x, const float* __restrict__ gamma,
            const float* __restrict__ beta,
            __nv_bfloat16* __restrict__ fh, __nv_bfloat16* __restrict__ fl)
{
    extern __shared__ float Us[];
    const int tid = threadIdx.x;
    const int tt = blockIdx.x & 31;
    const int qt = (blockIdx.x >> 5) & 3;
    const int b  = blockIdx.x >> 7;
    const int t0 = tt*8, q0 = qt*32;
    auto UI = [&](int tl, int c, int q) -> float& { return Us[(tl*64 + c)*33 + q]; };

    #pragma unroll
    for (int it = 0; it < 72; it++) {
        int idx = it*256 + tid;
        int q = idx & 31, c = (idx >> 5) & 63, tl = idx >> 11;
        int t = t0 + tl;
        UI(tl, c, q) = (t < 256) ? x[(((size_t)b*64 + c)*256 + t)*128 + q0 + q] : 0.f;
    }
    __syncthreads();
    for (int pair = tid; pair < 288; pair += 256) {
        int tl = pair >> 5, q = pair & 31;
        float sum = 0.f, sq = 0.f;
        #pragma unroll 8
        for (int c = 0; c < 64; c++) { float v = UI(tl, c, q); sum += v; sq += v*v; }
        float mu  = sum * (1.f/64.f);
        float inv = rsqrtf(sq * (1.f/64.f) - mu*mu + 1e-5f);
        #pragma unroll 8
        for (int c = 0; c < 64; c++)
            UI(tl, c, q) = (UI(tl, c, q) - mu) * inv * gamma[c] + beta[c];
    }
    __syncthreads();
    uint32_t* fhp = reinterpret_cast<uint32_t*>(fh);
    uint32_t* flp = reinterpret_cast<uint32_t*>(fl);
    #pragma unroll 4
    for (int it = 0; it < 64; it++) {
        int idx = it*256 + tid;
        int c = idx & 63, tl = (idx >> 6) & 7, q = idx >> 9;
        int l = t0 + tl;
        if (l >= 255) continue;
        uint32_t hp, lp;
        bsplit2(UI(tl, c, q), UI(tl+1, c, q), hp, lp);
        size_t o = ((size_t)(b*128 + q0 + q)*255 + l)*64 + c;
        fhp[o] = hp; flp[o] = lp;
    }
}

// ---------------------------------------------------------------------------
// GLA v6 (validated R14): register S master + warp-shuffle cumsum.
// ---------------------------------------------------------------------------
constexpr int G_SH = 0,     G_SL = 8192;
constexpr int G_QH = 16384, G_QL = 20480, G_KH = 24576, G_KL = 28672;
constexpr int G_VH = 32768, G_VL = 36864, G_AH = 40960, G_AL = 45056;
constexpr int G_U  = 49152, G_GL = 57856, GSM = 58112;

__global__ void __launch_bounds__(256, 3)
gla_kernel(const float* __restrict__ qkvr, const float* __restrict__ gkb,
           const float* __restrict__ gnp,
           __nv_bfloat16* __restrict__ ogh, __nv_bfloat16* __restrict__ ogl,
           int L, int nc, int order, int Nseq)
{
    extern __shared__ char smem[];
    const uint32_t sb = s2u(smem);
    float* Uf  = reinterpret_cast<float*>(smem + G_U);
    float* glf = reinterpret_cast<float*>(smem + G_GL);
    const int n = blockIdx.x >> 2, h = blockIdx.x & 3;
    const int tid = threadIdx.x, lane = tid & 31, w = tid >> 5;

    float sreg[4][4];
    #pragma unroll
    for (int i = 0; i < 4; i++)
        #pragma unroll
        for (int j = 0; j < 4; j++) sreg[i][j] = 0.f;

    for (int i = tid; i < 16384/4; i += 256) reinterpret_cast<uint32_t*>(smem)[i] = 0u;
    __syncthreads();

    for (int c = 0; c < nc; c++) {
        const int lbase = c * 32;
        #pragma unroll
        for (int r = 0; r < 2; r++) {
            int i = tid + r*256, t = i >> 4, d4 = (i & 15) * 4, l = lbase + t;
            float4 gv = make_float4(0,0,0,0);
            if (l < L)
                gv = *reinterpret_cast<const float4*>(&gkb[((size_t)(n*L + l))*256 + h*64 + d4]);
            *reinterpret_cast<float4*>(&Uf[t*68 + d4]) = gv;
        }
        __syncthreads();
        {
            float v[8];
            #pragma unroll
            for (int j = 0; j < 8; j++) v[j] = Uf[lane*68 + w*8 + j];
            #pragma unroll
            for (int off = 1; off < 32; off <<= 1) {
                #pragma unroll
                for (int j = 0; j < 8; j++) {
                    float up = __shfl_up_sync(0xFFFFFFFFu, v[j], off);
                    if (lane >= off) v[j] += up;
                }
            }
            #pragma unroll
            for (int j = 0; j < 8; j++) {
                Uf[lane*68 + w*8 + j] = v[j];
                if (lane == 31) glf[w*8 + j] = v[j];
            }
        }
        __syncthreads();
        #pragma unroll
        for (int r = 0; r < 2; r++) {
            int i = tid + r*256, t = i >> 4, d4 = (i & 15) * 4, l = lbase + t;
            float4 qv = make_float4(0,0,0,0), kv = qv, vv = qv;
            if (l < L) {
                size_t base = ((size_t)(n*L + l))*1024 + h*64 + d4;
                qv = *reinterpret_cast<const float4*>(&qkvr[base]);
                kv = *reinterpret_cast<const float4*>(&qkvr[base + 256]);
                vv = *reinterpret_cast<const float4*>(&qkvr[base + 512]);
                float4 g = *reinterpret_cast<const float4*>(&Uf[t*68 + d4]);
                qv.x *= __expf(g.x);  qv.y *= __expf(g.y);
                qv.z *= __expf(g.z);  qv.w *= __expf(g.w);
                kv.x *= __expf(-g.x); kv.y *= __expf(-g.y);
                kv.z *= __expf(-g.z); kv.w *= __expf(-g.w);
            }
            uint32_t off = SWZ(t*128 + d4*2);
            uint32_t h0, l0, h1, l1;
            bsplit2(qv.x, qv.y, h0, l0); bsplit2(qv.z, qv.w, h1, l1);
            *reinterpret_cast<uint2*>(smem + G_QH + off) = make_uint2(h0, h1);
            *reinterpret_cast<uint2*>(smem + G_QL + off) = make_uint2(l0, l1);
            bsplit2(kv.x, kv.y, h0, l0); bsplit2(kv.z, kv.w, h1, l1);
            *reinterpret_cast<uint2*>(smem + G_KH + off) = make_uint2(h0, h1);
            *reinterpret_cast<uint2*>(smem + G_KL + off) = make_uint2(l0, l1);
            bsplit2(vv.x, vv.y, h0, l0); bsplit2(vv.z, vv.w, h1, l1);
            *reinterpret_cast<uint2*>(smem + G_VH + off) = make_uint2(h0, h1);
            *reinterpret_cast<uint2*>(smem + G_VL + off) = make_uint2(l0, l1);
        }
        __syncthreads();
        // A = QK^T masked
        {
            const int mrow = 16*(w & 1) + (lane & 15);
            const int s0   = 8*(w >> 1);
            uint32_t kbh[2][4], kbl[2][4];
            #pragma unroll
            for (int g = 0; g < 2; g++) {
                uint32_t off = SWZ((s0 + (lane & 7))*128 + (g*32 + (lane >> 3)*8)*2);
                ldm4(kbh[g], sb + G_KH + off);
                ldm4(kbl[g], sb + G_KL + off);
            }
            float dA[4] = {0,0,0,0};
            #pragma unroll
            for (int ks = 0; ks < 4; ks++) {
                uint32_t ah[4], al[4];
                uint32_t aoff = SWZ(mrow*128 + (ks*16 + (lane >> 4)*8)*2);
                ldm4(ah, sb + G_QH + aoff);
                ldm4(al, sb + G_QL + aoff);
                uint32_t b0h = kbh[ks>>1][(ks&1)*2], b1h = kbh[ks>>1][(ks&1)*2+1];
                uint32_t b0l = kbl[ks>>1][(ks&1)*2], b1l = kbl[ks>>1][(ks&1)*2+1];
                mma16816(dA, ah, b0h, b1h);
                mma16816(dA, ah, b0l, b1l);
                mma16816(dA, al, b0h, b1h);
            }
            int r0 = 16*(w & 1) + (lane >> 2);
            int cc = s0 + 2*(lane & 3);
            float v00 = (cc   <= r0  ) ? dA[0] : 0.f;
            float v01 = (cc+1 <= r0  ) ? dA[1] : 0.f;
            float v10 = (cc   <= r0+8) ? dA[2] : 0.f;
            float v11 = (cc+1 <= r0+8) ? dA[3] : 0.f;
            uint32_t hp, lp;
            bsplit2(v00, v01, hp, lp);
            *reinterpret_cast<uint32_t*>(smem + G_AH + SWZ(r0*128 + cc*2)) = hp;
            *reinterpret_cast<uint32_t*>(smem + G_AL + SWZ(r0*128 + cc*2)) = lp;
            bsplit2(v10, v11, hp, lp);
            *reinterpret_cast<uint32_t*>(smem + G_AH + SWZ((r0+8)*128 + cc*2)) = hp;
            *reinterpret_cast<uint32_t*>(smem + G_AL + SWZ((r0+8)*128 + cc*2)) = lp;
        }
        __syncthreads();
        // o = A@V + Q@S(old) -> U
        {
            const int mrow = 16*(w & 1) + (lane & 15);
            const int nv0  = 16*(w >> 1);
            float d0[4] = {0,0,0,0}, d1[4] = {0,0,0,0};
            #pragma unroll
            for (int ks = 0; ks < 2; ks++) {
                uint32_t ah[4], al[4], vh[4], vl[4];
                uint32_t aoff = SWZ(mrow*128 + (ks*16 + (lane >> 4)*8)*2);
                ldm4(ah, sb + G_AH + aoff);
                ldm4(al, sb + G_AL + aoff);
                uint32_t boff = SWZ((ks*16 + ((lane >> 3) & 1)*8 + (lane & 7))*128
                                    + (nv0 + (lane >> 4)*8)*2);
                ldm4t(vh, sb + G_VH + boff);
                ldm4t(vl, sb + G_VL + boff);
                mma16816(d0, ah, vh[0], vh[1]);
                mma16816(d0, ah, vl[0], vl[1]);
                mma16816(d0, al, vh[0], vh[1]);
                mma16816(d1, ah, vh[2], vh[3]);
                mma16816(d1, ah, vl[2], vl[3]);
                mma16816(d1, al, vh[2], vh[3]);
            }
            #pragma unroll
            for (int ks = 0; ks < 4; ks++) {
                uint32_t qh[4], ql[4], sh[4], sl[4];
                uint32_t aoff = SWZ(mrow*128 + (ks*16 + (lane >> 4)*8)*2);
                ldm4(qh, sb + G_QH + aoff);
                ldm4(ql, sb + G_QL + aoff);
                uint32_t boff = SWZ((ks*16 + ((lane >> 3) & 1)*8 + (lane & 7))*128
                                    + (nv0 + (lane >> 4)*8)*2);
                ldm4t(sh, sb + G_SH + boff);
                ldm4t(sl, sb + G_SL + boff);
                mma16816(d0, qh, sh[0], sh[1]);
                mma16816(d0, qh, sl[0], sl[1]);
                mma16816(d0, ql, sh[0], sh[1]);
                mma16816(d1, qh, sh[2], sh[3]);
                mma16816(d1, qh, sl[2], sl[3]);
                mma16816(d1, ql, sh[2], sh[3]);
            }
            int r0 = 16*(w & 1) + (lane >> 2);
            int c0 = nv0 + 2*(lane & 3);
            *reinterpret_cast<float2*>(&Uf[r0*68 + c0])         = make_float2(d0[0], d0[1]);
            *reinterpret_cast<float2*>(&Uf[(r0+8)*68 + c0])     = make_float2(d0[2], d0[3]);
            *reinterpret_cast<float2*>(&Uf[r0*68 + c0 + 8])     = make_float2(d1[0], d1[1]);
            *reinterpret_cast<float2*>(&Uf[(r0+8)*68 + c0 + 8]) = make_float2(d1[2], d1[3]);
        }
        __syncthreads();
        // gate epilogue -> og hi/lo
        {
            int t = tid >> 3, dv0 = (tid & 7) * 8;
            float4 oa = *reinterpret_cast<const float4*>(&Uf[t*68 + dv0]);
            float4 obv = *reinterpret_cast<const float4*>(&Uf[t*68 + dv0 + 4]);
            float o8[8] = {oa.x,oa.y,oa.z,oa.w,obv.x,obv.y,obv.z,obv.w};
            float ss = 0.f;
            #pragma unroll
            for (int j = 0; j < 8; j++) ss += o8[j]*o8[j];
            ss += __shfl_xor_sync(0xFFFFFFFFu, ss, 4, 8);
            ss += __shfl_xor_sync(0xFFFFFFFFu, ss, 2, 8);
            ss += __shfl_xor_sync(0xFFFFFFFFu, ss, 1, 8);
            float inv = rsqrtf(ss * (1.f/64.f) + 1e-5f);
            int l = lbase + t;
            if (l < L) {
                size_t rb = ((size_t)(n*L + l))*1024 + 768 + h*64 + dv0;
                float4 r0 = *reinterpret_cast<const float4*>(&qkvr[rb]);
                float4 r1 = *reinterpret_cast<const float4*>(&qkvr[rb + 4]);
                float4 g0 = *reinterpret_cast<const float4*>(&gnp[h*64 + dv0]);
                float4 g1 = *reinterpret_cast<const float4*>(&gnp[h*64 + dv0 + 4]);
                float rr[8] = {r0.x,r0.y,r0.z,r0.w,r1.x,r1.y,r1.z,r1.w};
                float gg[8] = {g0.x,g0.y,g0.z,g0.w,g1.x,g1.y,g1.z,g1.w};
                float res[8];
                #pragma unroll
                for (int j = 0; j < 8; j++)
                    res[j] = o8[j] * inv * gg[j] * (rr[j] / (1.f + __expf(-rr[j])));
                uint32_t hq[4], lq[4];
                #pragma unroll
                for (int j = 0; j < 4; j++) bsplit2(res[2*j], res[2*j+1], hq[j], lq[j]);
                size_t tok = order ? ((size_t)l*Nseq + n) : ((size_t)n*L + l);
                size_t o = (tok*256 + h*64 + dv0) >> 1;
                *reinterpret_cast<uint4*>(reinterpret_cast<uint32_t*>(ogh) + o)
                    = make_uint4(hq[0], hq[1], hq[2], hq[3]);
                *reinterpret_cast<uint4*>(reinterpret_cast<uint32_t*>(ogl) + o)
                    = make_uint4(lq[0], lq[1], lq[2], lq[3]);
            }
        }
        // S update (register master)
        {
            const int mk0 = 16*(w & 3);
            const int nb  = 32*(w >> 2);
            float dd[4][4];
            #pragma unroll
            for (int i = 0; i < 4; i++)
                #pragma unroll
                for (int j = 0; j < 4; j++) dd[i][j] = 0.f;
            #pragma unroll
            for (int ks = 0; ks < 2; ks++) {
                uint32_t kh[4], kl[4];
                uint32_t aoff = SWZ((ks*16 + ((lane >> 3) >> 1)*8 + (lane & 7))*128
                                    + (mk0 + ((lane >> 3) & 1)*8)*2);
                ldm4t(kh, sb + G_KH + aoff);
                ldm4t(kl, sb + G_KL + aoff);
                #pragma unroll
                for (int np = 0; np < 2; np++) {
                    uint32_t vh[4], vl[4];
                    uint32_t boff = SWZ((ks*16 + ((lane >> 3) & 1)*8 + (lane & 7))*128
                                        + (nb + 16*np + (lane >> 4)*8)*2);
                    ldm4t(vh, sb + G_VH + boff);
                    ldm4t(vl, sb + G_VL + boff);
                    mma16816(dd[np*2],   kh, vh[0], vh[1]);
                    mma16816(dd[np*2],   kh, vl[0], vl[1]);
                    mma16816(dd[np*2],   kl, vh[0], vh[1]);
                    mma16816(dd[np*2+1], kh, vh[2], vh[3]);
                    mma16816(dd[np*2+1], kh, vl[2], vl[3]);
                    mma16816(dd[np*2+1], kl, vh[2], vh[3]);
                }
            }
            int r0 = mk0 + (lane >> 2);
            float e0 = __expf(glf[r0]);
            float e1 = __expf(glf[r0 + 8]);
            #pragma unroll
            for (int tile = 0; tile < 4; tile++) {
                int cc = nb + ((tile >> 1) * 16) + ((tile & 1) * 8) + 2*(lane & 3);
                float s00 = e0*(sreg[tile][0] + dd[tile][0]);
                float s01 = e0*(sreg[tile][1] + dd[tile][1]);
                float s10 = e1*(sreg[tile][2] + dd[tile][2]);
                float s11 = e1*(sreg[tile][3] + dd[tile][3]);
                sreg[tile][0] = s00; sreg[tile][1] = s01;
                sreg[tile][2] = s10; sreg[tile][3] = s11;
                uint32_t hp, lp;
                bsplit2(s00, s01, hp, lp);
                *reinterpret_cast<uint32_t*>(smem + G_SH + SWZ(r0*128 + cc*2)) = hp;
                *reinterpret_cast<uint32_t*>(smem + G_SL + SWZ(r0*128 + cc*2)) = lp;
                bsplit2(s10, s11, hp, lp);
                *reinterpret_cast<uint32_t*>(smem + G_SH + SWZ((r0+8)*128 + cc*2)) = hp;
                *reinterpret_cast<uint32_t*>(smem + G_SL + SWZ((r0+8)*128 + cc*2)) = lp;
            }
        }
        __syncthreads();
    }
}

// ---------------------------------------------------------------------------
// combine kernels (validated R12)
// ---------------------------------------------------------------------------
__global__ void __launch_bounds__(256)
combine0_kernel(const float* __restrict__ d01, const float* __restrict__ ctb,
                const float* __restrict__ resid, float* __restrict__ out)
{
    extern __shared__ float sm[];
    const int tid = threadIdx.x;
    const int n = blockIdx.x;
    const int b = n >> 8, t = n & 255;
    for (int i = tid; i < 127*128; i += 256) {
        int tok = i >> 7, col = i & 127;
        sm[tok*129 + col] = d01[((size_t)n*127 + tok)*128 + col];
    }
    __syncthreads();
    #pragma unroll 4
    for (int i = tid; i < 8192; i += 256) {
        int q = i & 127, c = i >> 7;
        size_t oidx = (((size_t)b*64 + c)*256 + t)*128 + q;
        float acc = resid[oidx] + ctb[c];
        if (q < 127) acc += sm[q*129 + 2*c];
        if (q >= 1)  acc += sm[(q-1)*129 + 2*c + 1];
        out[oidx] = acc;
    }
}

__global__ void combine1_kernel(const float* __restrict__ d01T, const float* __restrict__ ctb,
                                const float* __restrict__ resid, float* __restrict__ out)
{
    int idx = blockIdx.x * blockDim.x + threadIdx.x;
    if (idx >= ELEMS) return;
    int q = idx & 127, t = (idx >> 7) & 255, c = (idx >> 15) & 63, b = idx >> 21;
    float acc = resid[idx] + ctb[c];
    int mcur = t*512 + b*128 + q;
    if (t < 255) acc += d01T[(size_t)(2*c)*MAXTOK + mcur];
    if (t >= 1)  acc += d01T[(size_t)(2*c + 1)*MAXTOK + mcur - 512];
    out[idx] = acc;
}

struct WPtrs {
    __nv_bfloat16 *wch[2], *wcl[2], *wfT_h[2], *wfT_l[2], *fh, *fl, *ogh, *ogl;
};
constexpr int HSM2  = 131072;
constexpr int LN1SM = 9*64*33*4;
constexpr int C0SM  = 127*129*4;

static void run_pass(const float* input, const float* gamma, const float* beta,
                     const float* gn, const float* ctb,
                     const float* resid, float* out,
                     float* A, const WPtrs& W, int pass)
{
    const int N   = pass == 0 ? 1024 : 512;
    const int L   = pass == 0 ? 127  : 255;
    const int nc  = pass == 0 ? 4    : 8;
    const int tok = N * L;
    const int Mt  = tok / 128;

    float* qkvr = A + OF_QKVR;
    float* gk   = A + OF_GK;
    float* d01  = A + OF_D01;

    if (pass == 0) lnf0_kernel<<<1024, 128>>>(input, gamma, beta, W.fh, W.fl);
    else           lnf1_kernel<<<512, 256, LN1SM>>>(input, gamma, beta, W.fh, W.fl);
    hg2c<<<dim3(10, Mt), 256, HSM2>>>(W.fh, W.fl, W.wch[pass], W.wcl[pass], qkvr, gk, tok);
    gla_kernel<<<N*4, 256, GSM>>>(qkvr, gk, gn, W.ogh, W.ogl, L, nc, pass, N);
    hg2<<<dim3(Mt, 1), 256, HSM2>>>(W.ogh, W.ogl, W.wfT_h[pass], W.wfT_l[pass],
                                    d01, tok, 128, 256, pass);
    if (pass == 0) combine0_kernel<<<1024, 256, C0SM>>>(d01, ctb, resid, out);
    else           combine1_kernel<<<CDIV(ELEMS, 256), 256>>>(d01, ctb, resid, out);
}

extern "C" void kernel_launch(void* const* d_in, const int* in_sizes, int n_in,
                              void* d_out, int out_size)
{
    const float* x = (const float*)d_in[0];
    auto P = [&](int i) { return (const float*)d_in[i]; };

    float* arena = nullptr;
    cudaGetSymbolAddress((void**)&arena, g_arena);
    float* y4 = arena + OF_Y4;

    WPtrs W;
    {
        __nv_bfloat16* p;
        cudaGetSymbolAddress((void**)&p, g_wcat_h); W.wch[0] = p; W.wch[1] = p + 1280*128;
        cudaGetSymbolAddress((void**)&p, g_wcat_l); W.wcl[0] = p; W.wcl[1] = p + 1280*128;
        cudaGetSymbolAddress((void**)&p, g_wfT_h);  W.wfT_h[0] = p; W.wfT_h[1] = p + 128*256;
        cudaGetSymbolAddress((void**)&p, g_wfT_l);  W.wfT_l[0] = p; W.wfT_l[1] = p + 128*256;
    }
    cudaGetSymbolAddress((void**)&W.fh,  g_fh);
    cudaGetSymbolAddress((void**)&W.fl,  g_fl);
    cudaGetSymbolAddress((void**)&W.ogh, g_ogh);
    cudaGetSymbolAddress((void**)&W.ogl, g_ogl);

    cudaFuncSetAttribute(hg2c, cudaFuncAttributeMaxDynamicSharedMemorySize, HSM2);
    cudaFuncSetAttribute(hg2,  cudaFuncAttributeMaxDynamicSharedMemorySize, HSM2);
    cudaFuncSetAttribute(gla_kernel,  cudaFuncAttributeMaxDynamicSharedMemorySize, GSM);
    cudaFuncSetAttribute(lnf1_kernel, cudaFuncAttributeMaxDynamicSharedMemorySize, LN1SM);
    cudaFuncSetAttribute(combine0_kernel, cudaFuncAttributeMaxDynamicSharedMemorySize, C0SM);

    // Both weight preps upfront — pass-1 prep overlaps pass-0's pipeline.
    prep_kernel<<<768, 256>>>(P(4), P(5), P(6), P(9), P(7), P(8), P(11), P(12),
                              W.wch[0], W.wcl[0], W.wfT_h[0], W.wfT_l[0]);
    prep_kernel<<<768, 256>>>(P(16), P(17), P(18), P(21), P(19), P(20), P(23), P(24),
                              W.wch[1], W.wcl[1], W.wfT_h[1], W.wfT_l[1]);

    // Pass 0 (intra): gamma=2 beta=3 gn=10 ctb=13
    run_pass(x, P(2), P(3), P(10), P(13), x, y4, arena, W, 0);
    // Pass 1 (inter): gamma=14 beta=15 gn=22 ctb=25
    run_pass(y4, P(14), P(15), P(22), P(25), y4, (float*)d_out, arena, W, 1);
}

// round 17
// speedup vs baseline: 1.2015x; 1.1032x over previous
#include <cuda_runtime.h>
#include <cuda_bf16.h>
#include <math.h>
#include <stdint.h>

#define CDIV(a,b) (((a)+(b)-1)/(b))
typedef unsigned long long ull;

constexpr int MAXTOK = 130560;
constexpr int ELEMS  = 4*64*256*128;

constexpr size_t OF_QKVR = 0;
constexpr size_t OF_GK   = OF_QKVR + (size_t)MAXTOK*1024;
constexpr size_t OF_D01  = OF_GK   + (size_t)MAXTOK*256;
constexpr size_t OF_Y4   = OF_D01  + (size_t)MAXTOK*128;
constexpr size_t ARENA_TOTAL = OF_Y4 + (size_t)ELEMS;

__device__ __align__(128) float g_arena[ARENA_TOTAL];
__device__ __align__(128) __nv_bfloat16 g_fh[(size_t)MAXTOK*128];
__device__ __align__(128) __nv_bfloat16 g_fl[(size_t)MAXTOK*128];
__device__ __align__(128) __nv_bfloat16 g_ogh[(size_t)MAXTOK*256];
__device__ __align__(128) __nv_bfloat16 g_ogl[(size_t)MAXTOK*256];
__device__ __align__(128) __nv_bfloat16 g_wcat_h[1280*128];   // wp | wgg
__device__ __align__(128) __nv_bfloat16 g_wcat_l[1280*128];
__device__ __align__(128) __nv_bfloat16 g_wfT_h[128*256];
__device__ __align__(128) __nv_bfloat16 g_wfT_l[128*256];

__device__ __forceinline__ void bsplit(float x, __nv_bfloat16& h, __nv_bfloat16& l) {
    h = __float2bfloat16_rn(x);
    l = __float2bfloat16_rn(x - __bfloat162float(h));
}
__device__ __forceinline__ uint32_t pkbf(float x, float y) {
    uint32_t r; asm("cvt.rn.bf16x2.f32 %0, %1, %2;" : "=r"(r) : "f"(y), "f"(x)); return r;
}
__device__ __forceinline__ void bsplit2(float x0, float x1, uint32_t& hp, uint32_t& lp) {
    hp = pkbf(x0, x1);
    float h0 = __uint_as_float(hp << 16);
    float h1 = __uint_as_float(hp & 0xFFFF0000u);
    lp = pkbf(x0 - h0, x1 - h1);
}

// ---------------------------------------------------------------------------
// Fused weight prep (validated R10)
// ---------------------------------------------------------------------------
__global__ void prep_kernel(const float* __restrict__ Wq, const float* __restrict__ Wk,
                            const float* __restrict__ Wv, const float* __restrict__ Wr,
                            const float* __restrict__ Wg1, const float* __restrict__ Wg2,
                            const float* __restrict__ Wo, const float* __restrict__ ctw,
                            __nv_bfloat16* __restrict__ wch, __nv_bfloat16* __restrict__ wcl,
                            __nv_bfloat16* __restrict__ wfh, __nv_bfloat16* __restrict__ wfl)
{
    const int blk = blockIdx.x;
    if (blk < 512) {
        int idx = blk * 256 + threadIdx.x;
        int n = idx >> 7, k = idx & 127;
        int grp = n >> 8, nn = n & 255;
        const float* W = (grp == 0) ? Wq : (grp == 1) ? Wk : (grp == 2) ? Wv : Wr;
        float x = W[k*256 + nn] * ((grp == 0) ? 0.125f : 1.f);
        __nv_bfloat16 h, l; bsplit(x, h, l);
        wch[idx] = h; wcl[idx] = l;
    } else if (blk < 640) {
        int idx = (blk - 512) * 256 + threadIdx.x;
        int n = idx >> 7, k = idx & 127;
        float s = 0.f;
        #pragma unroll
        for (int j = 0; j < 32; j++) s += __ldg(&Wg1[k*32 + j]) * __ldg(&Wg2[j*256 + n]);
        __nv_bfloat16 h, l; bsplit(s, h, l);
        wch[1024*128 + idx] = h; wcl[1024*128 + idx] = l;
    } else {
        int idx = (blk - 640) * 256 + threadIdx.x;
        int n = idx >> 8, k = idx & 255;
        float s = 0.f;
        #pragma unroll 8
        for (int j = 0; j < 128; j++) s += __ldg(&Wo[k*128 + j]) * __ldg(&ctw[j*128 + n]);
        __nv_bfloat16 h, l; bsplit(s, h, l);
        wfh[idx] = h; wfl[idx] = l;
    }
}

__device__ __forceinline__ uint32_t s2u(const void* p) {
    uint32_t a;
    asm("{ .reg .u64 t; cvta.to.shared.u64 t, %1; cvt.u32.u64 %0, t; }" : "=r"(a) : "l"(p));
    return a;
}
#define SWZ(x) ((x) ^ (((x) >> 3) & 0x70))
__device__ __forceinline__ void ldm4(uint32_t* r, uint32_t addr) {
    asm volatile("ldmatrix.sync.aligned.m8n8.x4.shared.b16 {%0,%1,%2,%3}, [%4];"
        : "=r"(r[0]), "=r"(r[1]), "=r"(r[2]), "=r"(r[3]) : "r"(addr));
}
__device__ __forceinline__ void ldm4t(uint32_t* r, uint32_t addr) {
    asm volatile("ldmatrix.sync.aligned.m8n8.x4.trans.shared.b16 {%0,%1,%2,%3}, [%4];"
        : "=r"(r[0]), "=r"(r[1]), "=r"(r[2]), "=r"(r[3]) : "r"(addr));
}
__device__ __forceinline__ void mma16816(float* d, const uint32_t* a, uint32_t b0, uint32_t b1) {
    asm volatile("mma.sync.aligned.m16n8k16.row.col.f32.bf16.bf16.f32 "
        "{%0,%1,%2,%3}, {%4,%5,%6,%7}, {%8,%9}, {%0,%1,%2,%3};"
        : "+f"(d[0]), "+f"(d[1]), "+f"(d[2]), "+f"(d[3])
        : "r"(a[0]), "r"(a[1]), "r"(a[2]), "r"(a[3]), "r"(b0), "r"(b1));
}
#define CPA16(dst, src) \
    asm volatile("cp.async.cg.shared.global [%0], [%1], 16;" :: "r"(dst), "l"(src))

// ---------------------------------------------------------------------------
// Shared GEMM mainloop (validated, used by hg2)
// ---------------------------------------------------------------------------
struct GemmCtx {
    uint32_t sb; int tid, lane, w, m0w, n0w, lrow, lk8;
};
__device__ __forceinline__ void gemm_main(
    GemmCtx& g, float d[2][8][4],
    const __nv_bfloat16* Ah, const __nv_bfloat16* Al,
    const __nv_bfloat16* Bh, const __nv_bfloat16* Bl,
    int m0, int bn0, int K)
{
    auto issue = [&](int ch, int st) {
        const int kc0 = ch << 6;
        const uint32_t sbase = g.sb + st*65536;
        #pragma unroll
        for (int it = 0; it < 4; it++) {
            int i = g.tid + it*256;
            int r = i >> 3, gg = i & 7;
            uint32_t doff = SWZ(r*128 + gg*16);
            size_t aoff = (size_t)(m0 + r)*K + kc0 + gg*8;
            size_t boff = (size_t)(bn0 + r)*K + kc0 + gg*8;
            CPA16(sbase +         doff, Ah + aoff);
            CPA16(sbase + 16384 + doff, Al + aoff);
            CPA16(sbase + 32768 + doff, Bh + boff);
            CPA16(sbase + 49152 + doff, Bl + boff);
        }
        asm volatile("cp.async.commit_group;" ::: "memory");
    };
    const int nch = K >> 6;
    issue(0, 0);
    for (int ch = 0; ch < nch; ch++) {
        const bool nxt = (ch + 1) < nch;
        if (nxt) issue(ch + 1, (ch + 1) & 1);
        if (nxt) asm volatile("cp.async.wait_group 1;" ::: "memory");
        else     asm volatile("cp.async.wait_group 0;" ::: "memory");
        __syncthreads();
        const uint32_t sbase = g.sb + (ch & 1)*65536;
        #pragma unroll
        for (int ks = 0; ks < 4; ks++) {
            const int kcol = ks*16 + g.lk8;
            uint32_t ah[2][4], al2[2][4], bb[4][4];
            #pragma unroll
            for (int mt = 0; mt < 2; mt++) {
                uint32_t off = SWZ((g.m0w + mt*16 + g.lrow)*128 + kcol*2);
                ldm4(ah[mt],  sbase + off);
                ldm4(al2[mt], sbase + 16384 + off);
            }
            #pragma unroll
            for (int nt2 = 0; nt2 < 4; nt2++) {
                uint32_t off = SWZ((g.n0w + nt2*16 + g.lrow)*128 + kcol*2);
                ldm4(bb[nt2], sbase + 32768 + off);
            }
            #pragma unroll
            for (int mt = 0; mt < 2; mt++)
                #pragma unroll
                for (int nt = 0; nt < 8; nt++) {
                    uint32_t b0 = (nt & 1) ? bb[nt>>1][1] : bb[nt>>1][0];
                    uint32_t b1 = (nt & 1) ? bb[nt>>1][3] : bb[nt>>1][2];
                    mma16816(d[mt][nt], ah[mt],  b0, b1);
                    mma16816(d[mt][nt], al2[mt], b0, b1);
                }
            #pragma unroll
            for (int nt2 = 0; nt2 < 4; nt2++) {
                uint32_t off = SWZ((g.n0w + nt2*16 + g.lrow)*128 + kcol*2);
                ldm4(bb[nt2], sbase + 49152 + off);
            }
            #pragma unroll
            for (int mt = 0; mt < 2; mt++)
                #pragma unroll
                for (int nt = 0; nt < 8; nt++) {
                    uint32_t b0 = (nt & 1) ? bb[nt>>1][1] : bb[nt>>1][0];
                    uint32_t b1 = (nt & 1) ? bb[nt>>1][3] : bb[nt>>1][2];
                    mma16816(d[mt][nt], ah[mt], b0, b1);
                }
        }
        __syncthreads();
    }
}
__device__ __forceinline__ GemmCtx mk_ctx(uint32_t sb) {
    GemmCtx g;
    g.tid = threadIdx.x; g.lane = g.tid & 31; g.w = g.tid >> 5;
    g.m0w = (g.w & 3) * 32; g.n0w = (g.w >> 2) * 64;
    g.lrow = g.lane & 15; g.lk8 = (g.lane >> 4) << 3;
    g.sb = sb;
    return g;
}

// ---------------------------------------------------------------------------
// hg2c v2: 128x64 tile, 2 CTAs/SM. Grid (20, Mt); yi<16 -> qkvr, yi>=16 -> gk.
// Stage = Ah 16K | Al 16K | Bh 8K | Bl 8K = 48KB; 2 stages = 96KB.
// Same chunk/kstep/hi-lo mma order as validated kernel -> bit-identical math.
// ---------------------------------------------------------------------------
constexpr int HSMC = 98304;
__global__ void __launch_bounds__(256, 2)
hg2c(const __nv_bfloat16* __restrict__ Ah, const __nv_bfloat16* __restrict__ Al,
     const __nv_bfloat16* __restrict__ Bh, const __nv_bfloat16* __restrict__ Bl,
     float* __restrict__ Cq, float* __restrict__ Cg, int M)
{
    extern __shared__ char smem[];
    const uint32_t sb = s2u(smem);
    const int tid = threadIdx.x, lane = tid & 31, w = tid >> 5;
    const int m0w = (w & 3) * 32, n0w = (w >> 2) * 32;
    const int lrow = lane & 15, lk8 = (lane >> 4) << 3;
    const int m0  = blockIdx.y * 128;
    const int yi  = blockIdx.x;
    const int bn0 = yi * 64;                 // row offset into wcat [1280][128]

    auto issue = [&](int ch, int st) {
        const int kc0 = ch << 6;
        const uint32_t sbase = sb + st*49152;
        #pragma unroll
        for (int it = 0; it < 4; it++) {
            int i = tid + it*256;
            int r = i >> 3, gg = i & 7;
            uint32_t doff = SWZ(r*128 + gg*16);
            size_t aoff = (size_t)(m0 + r)*128 + kc0 + gg*8;
            CPA16(sbase +         doff, Ah + aoff);
            CPA16(sbase + 16384 + doff, Al + aoff);
            if (it < 2) {
                size_t boff = (size_t)(bn0 + r)*128 + kc0 + gg*8;
                CPA16(sbase + 32768 + doff, Bh + boff);
                CPA16(sbase + 40960 + doff, Bl + boff);
            }
        }
        asm volatile("cp.async.commit_group;" ::: "memory");
    };

    float d[2][4][4];
    #pragma unroll
    for (int mt = 0; mt < 2; mt++)
        #pragma unroll
        for (int nt = 0; nt < 4; nt++)
            #pragma unroll
            for (int u = 0; u < 4; u++) d[mt][nt][u] = 0.f;

    issue(0, 0);
    #pragma unroll
    for (int ch = 0; ch < 2; ch++) {
        const bool nxt = (ch + 1) < 2;
        if (nxt) issue(ch + 1, 1);
        if (nxt) asm volatile("cp.async.wait_group 1;" ::: "memory");
        else     asm volatile("cp.async.wait_group 0;" ::: "memory");
        __syncthreads();
        const uint32_t sbase = sb + ch*49152;
        #pragma unroll
        for (int ks = 0; ks < 4; ks++) {
            const int kcol = ks*16 + lk8;
            uint32_t ah[2][4], al2[2][4], bb[2][4];
            #pragma unroll
            for (int mt = 0; mt < 2; mt++) {
                uint32_t off = SWZ((m0w + mt*16 + lrow)*128 + kcol*2);
                ldm4(ah[mt],  sbase + off);
                ldm4(al2[mt], sbase + 16384 + off);
            }
            #pragma unroll
            for (int nt2 = 0; nt2 < 2; nt2++) {
                uint32_t off = SWZ((n0w + nt2*16 + lrow)*128 + kcol*2);
                ldm4(bb[nt2], sbase + 32768 + off);
            }
            #pragma unroll
            for (int mt = 0; mt < 2; mt++)
                #pragma unroll
                for (int nt = 0; nt < 4; nt++) {
                    uint32_t b0 = (nt & 1) ? bb[nt>>1][1] : bb[nt>>1][0];
                    uint32_t b1 = (nt & 1) ? bb[nt>>1][3] : bb[nt>>1][2];
                    mma16816(d[mt][nt], ah[mt],  b0, b1);
                    mma16816(d[mt][nt], al2[mt], b0, b1);
                }
            #pragma unroll
            for (int nt2 = 0; nt2 < 2; nt2++) {
                uint32_t off = SWZ((n0w + nt2*16 + lrow)*128 + kcol*2);
                ldm4(bb[nt2], sbase + 40960 + off);
            }
            #pragma unroll
            for (int mt = 0; mt < 2; mt++)
                #pragma unroll
                for (int nt = 0; nt < 4; nt++) {
                    uint32_t b0 = (nt & 1) ? bb[nt>>1][1] : bb[nt>>1][0];
                    uint32_t b1 = (nt & 1) ? bb[nt>>1][3] : bb[nt>>1][2];
                    mma16816(d[mt][nt], ah[mt], b0, b1);
                }
        }
        __syncthreads();
    }

    const bool isgk = yi >= 16;
    float* C   = isgk ? Cg : Cq;
    const int Nn = isgk ? 256 : 1024;
    const int nb = isgk ? (yi - 16) * 64 : yi * 64;
    const int er = lane >> 2, ec = (lane & 3) * 2;
    #pragma unroll
    for (int mt = 0; mt < 2; mt++) {
        #pragma unroll
        for (int nt = 0; nt < 4; nt++) {
            float v[4] = {d[mt][nt][0], d[mt][nt][1], d[mt][nt][2], d[mt][nt][3]};
            if (isgk) {
                #pragma unroll
                for (int u = 0; u < 4; u++)
                    v[u] = (fminf(v[u], 0.f) - log1pf(__expf(-fabsf(v[u])))) * (1.f/32.f);
            }
            size_t m = (size_t)(m0 + m0w + mt*16 + er);
            int    n = nb + n0w + nt*8 + ec;
            *reinterpret_cast<float2*>(&C[m*Nn + n])       = make_float2(v[0], v[1]);
            *reinterpret_cast<float2*>(&C[(m + 8)*Nn + n]) = make_float2(v[2], v[3]);
        }
    }
}

// d01 GEMM (og @ wf). trans=0: C[m][n]; trans=1: C[n][m] via smem transpose.
__global__ void __launch_bounds__(256, 1)
hg2(const __nv_bfloat16* __restrict__ Ah, const __nv_bfloat16* __restrict__ Al,
    const __nv_bfloat16* __restrict__ Bh, const __nv_bfloat16* __restrict__ Bl,
    float* __restrict__ C, int M, int N, int K, int trans)
{
    extern __shared__ char smem[];
    GemmCtx g = mk_ctx(s2u(smem));
    const int m0 = blockIdx.x * 128;
    const int n0 = blockIdx.y * 128;
    float d[2][8][4];
    #pragma unroll
    for (int mt = 0; mt < 2; mt++)
        #pragma unroll
        for (int nt = 0; nt < 8; nt++)
            #pragma unroll
            for (int u = 0; u < 4; u++) d[mt][nt][u] = 0.f;

    gemm_main(g, d, Ah, Al, Bh, Bl, m0, n0, K);

    const int er = g.lane >> 2, ec = (g.lane & 3) * 2;
    if (!trans) {
        #pragma unroll
        for (int mt = 0; mt < 2; mt++) {
            #pragma unroll
            for (int nt = 0; nt < 8; nt++) {
                size_t m = (size_t)(m0 + g.m0w + mt*16 + er);
                int    n = n0 + g.n0w + nt*8 + ec;
                *reinterpret_cast<float2*>(&C[m*N + n])       = make_float2(d[mt][nt][0], d[mt][nt][1]);
                *reinterpret_cast<float2*>(&C[(m + 8)*N + n]) = make_float2(d[mt][nt][2], d[mt][nt][3]);
            }
        }
    } else {
        float* sm = reinterpret_cast<float*>(smem);
        #pragma unroll
        for (int mt = 0; mt < 2; mt++) {
            #pragma unroll
            for (int nt = 0; nt < 8; nt++) {
                int r1 = g.m0w + mt*16 + er;
                int cb = g.n0w + nt*8 + ec;
                sm[r1*129 + cb]       = d[mt][nt][0];
                sm[r1*129 + cb + 1]   = d[mt][nt][1];
                sm[(r1+8)*129 + cb]     = d[mt][nt][2];
                sm[(r1+8)*129 + cb + 1] = d[mt][nt][3];
            }
        }
        __syncthreads();
        #pragma unroll
        for (int j = 0; j < 16; j++) {
            int col = g.w + 8*j;
            #pragma unroll
            for (int r = 0; r < 4; r++) {
                int row = g.lane + 32*r;
                C[(size_t)(n0 + col)*M + m0 + row] = sm[row*129 + col];
            }
        }
    }
}

// ---------------------------------------------------------------------------
// Fused LN + unfold (validated R9)
// ---------------------------------------------------------------------------
__global__ void __launch_bounds__(128)
lnf0_kernel(const float* __restrict__ x, const float* __restrict__ gamma,
            const float* __restrict__ beta,
            __nv_bfloat16* __restrict__ fh, __nv_bfloat16* __restrict__ fl)
{
    __shared__ float U[64][129];
    const int tid = threadIdx.x;
    const int b = blockIdx.x >> 8, t = blockIdx.x & 255;
    const int n = blockIdx.x;
    #pragma unroll 8
    for (int c = 0; c < 64; c++)
        U[c][tid] = x[(((size_t)b*64 + c)*256 + t)*128 + tid];
    __syncthreads();
    float sum = 0.f, sq = 0.f;
    #pragma unroll 8
    for (int c = 0; c < 64; c++) { float v = U[c][tid]; sum += v; sq += v*v; }
    float mu  = sum * (1.f/64.f);
    float inv = rsqrtf(sq * (1.f/64.f) - mu*mu + 1e-5f);
    #pragma unroll 8
    for (int c = 0; c < 64; c++)
        U[c][tid] = (U[c][tid] - mu) * inv * gamma[c] + beta[c];
    __syncthreads();
    uint32_t* fhp = reinterpret_cast<uint32_t*>(fh);
    uint32_t* flp = reinterpret_cast<uint32_t*>(fl);
    #pragma unroll 4
    for (int it = 0; it < 64; it++) {
        int idx = it*128 + tid;
        int l = idx >> 6, c = idx & 63;
        if (l >= 127) continue;
        uint32_t hp, lp;
        bsplit2(U[c][l], U[c][l+1], hp, lp);
        size_t o = (size_t)(n*127 + l)*64 + c;
        fhp[o] = hp; flp[o] = lp;
    }
}

__global__ void __launch_bounds__(256)
lnf1_kernel(const float* __restrict__ x, const float* __restrict__ gamma,
            const float* __restrict__ beta,
            __nv_bfloat16* __restrict__ fh, __nv_bfloat16* __restrict__ fl)
{
    extern __shared__ float Us[];
    const int tid = threadIdx.x;
    const int tt = blockIdx.x & 31;
    const int qt = (blockIdx.x >> 5) & 3;
    const int b  = blockIdx.x >> 7;
    const int t0 = tt*8, q0 = qt*32;
    auto UI = [&](int tl, int c, int q) -> float& { return Us[(tl*64 + c)*33 + q]; };

    #pragma unroll
    for (int it = 0; it < 72; it++) {
        int idx = it*256 + tid;
        int q = idx & 31, c = (idx >> 5) & 63, tl = idx >> 11;
        int t = t0 + tl;
        UI(tl, c, q) = (t < 256) ? x[(((size_t)b*64 + c)*256 + t)*128 + q0 + q] : 0.f;
    }
    __syncthreads();
    for (int pair = tid; pair < 288; pair += 256) {
        int tl = pair >> 5, q = pair & 31;
        float sum = 0.f, sq = 0.f;
        #pragma unroll 8
        for (int c = 0; c < 64; c++) { float v = UI(tl, c, q); sum += v; sq += v*v; }
        float mu  = sum * (1.f/64.f);
        float inv = rsqrtf(sq * (1.f/64.f) - mu*mu + 1e-5f);
        #pragma unroll 8
        for (int c = 0; c < 64; c++)
            UI(tl, c, q) = (UI(tl, c, q) - mu) * inv * gamma[c] + beta[c];
    }
    __syncthreads();
    uint32_t* fhp = reinterpret_cast<uint32_t*>(fh);
    uint32_t* flp = reinterpret_cast<uint32_t*>(fl);
    #pragma unroll 4
    for (int it = 0; it < 64; it++) {
        int idx = it*256 + tid;
        int c = idx & 63, tl = (idx >> 6) & 7, q = idx >> 9;
        int l = t0 + tl;
        if (l >= 255) continue;
        uint32_t hp, lp;
        bsplit2(UI(tl, c, q), UI(tl+1, c, q), hp, lp);
        size_t o = ((size_t)(b*128 + q0 + q)*255 + l)*64 + c;
        fhp[o] = hp; flp[o] = lp;
    }
}

// ---------------------------------------------------------------------------
// GLA v6 (validated R14): register S master + warp-shuffle cumsum.
// ---------------------------------------------------------------------------
constexpr int G_SH = 0,     G_SL = 8192;
constexpr int G_QH = 16384, G_QL = 20480, G_KH = 24576, G_KL = 28672;
constexpr int G_VH = 32768, G_VL = 36864, G_AH = 40960, G_AL = 45056;
constexpr int G_U  = 49152, G_GL = 57856, GSM = 58112;

__global__ void __launch_bounds__(256, 3)
gla_kernel(const float* __restrict__ qkvr, const float* __restrict__ gkb,
           const float* __restrict__ gnp,
           __nv_bfloat16* __restrict__ ogh, __nv_bfloat16* __restrict__ ogl,
           int L, int nc, int order, int Nseq)
{
    extern __shared__ char smem[];
    const uint32_t sb = s2u(smem);
    float* Uf  = reinterpret_cast<float*>(smem + G_U);
    float* glf = reinterpret_cast<float*>(smem + G_GL);
    const int n = blockIdx.x >> 2, h = blockIdx.x & 3;
    const int tid = threadIdx.x, lane = tid & 31, w = tid >> 5;

    float sreg[4][4];
    #pragma unroll
    for (int i = 0; i < 4; i++)
        #pragma unroll
        for (int j = 0; j < 4; j++) sreg[i][j] = 0.f;

    for (int i = tid; i < 16384/4; i += 256) reinterpret_cast<uint32_t*>(smem)[i] = 0u;
    __syncthreads();

    for (int c = 0; c < nc; c++) {
        const int lbase = c * 32;
        #pragma unroll
        for (int r = 0; r < 2; r++) {
            int i = tid + r*256, t = i >> 4, d4 = (i & 15) * 4, l = lbase + t;
            float4 gv = make_float4(0,0,0,0);
            if (l < L)
                gv = *reinterpret_cast<const float4*>(&gkb[((size_t)(n*L + l))*256 + h*64 + d4]);
            *reinterpret_cast<float4*>(&Uf[t*68 + d4]) = gv;
        }
        __syncthreads();
        {
            float v[8];
            #pragma unroll
            for (int j = 0; j < 8; j++) v[j] = Uf[lane*68 + w*8 + j];
            #pragma unroll
            for (int off = 1; off < 32; off <<= 1) {
                #pragma unroll
                for (int j = 0; j < 8; j++) {
                    float up = __shfl_up_sync(0xFFFFFFFFu, v[j], off);
                    if (lane >= off) v[j] += up;
                }
            }
            #pragma unroll
            for (int j = 0; j < 8; j++) {
                Uf[lane*68 + w*8 + j] = v[j];
                if (lane == 31) glf[w*8 + j] = v[j];
            }
        }
        __syncthreads();
        #pragma unroll
        for (int r = 0; r < 2; r++) {
            int i = tid + r*256, t = i >> 4, d4 = (i & 15) * 4, l = lbase + t;
            float4 qv = make_float4(0,0,0,0), kv = qv, vv = qv;
            if (l < L) {
                size_t base = ((size_t)(n*L + l))*1024 + h*64 + d4;
                qv = *reinterpret_cast<const float4*>(&qkvr[base]);
                kv = *reinterpret_cast<const float4*>(&qkvr[base + 256]);
                vv = *reinterpret_cast<const float4*>(&qkvr[base + 512]);
                float4 g = *reinterpret_cast<const float4*>(&Uf[t*68 + d4]);
                qv.x *= __expf(g.x);  qv.y *= __expf(g.y);
                qv.z *= __expf(g.z);  qv.w *= __expf(g.w);
                kv.x *= __expf(-g.x); kv.y *= __expf(-g.y);
                kv.z *= __expf(-g.z); kv.w *= __expf(-g.w);
            }
            uint32_t off = SWZ(t*128 + d4*2);
            uint32_t h0, l0, h1, l1;
            bsplit2(qv.x, qv.y, h0, l0); bsplit2(qv.z, qv.w, h1, l1);
            *reinterpret_cast<uint2*>(smem + G_QH + off) = make_uint2(h0, h1);
            *reinterpret_cast<uint2*>(smem + G_QL + off) = make_uint2(l0, l1);
            bsplit2(kv.x, kv.y, h0, l0); bsplit2(kv.z, kv.w, h1, l1);
            *reinterpret_cast<uint2*>(smem + G_KH + off) = make_uint2(h0, h1);
            *reinterpret_cast<uint2*>(smem + G_KL + off) = make_uint2(l0, l1);
            bsplit2(vv.x, vv.y, h0, l0); bsplit2(vv.z, vv.w, h1, l1);
            *reinterpret_cast<uint2*>(smem + G_VH + off) = make_uint2(h0, h1);
            *reinterpret_cast<uint2*>(smem + G_VL + off) = make_uint2(l0, l1);
        }
        __syncthreads();
        // A = QK^T masked
        {
            const int mrow = 16*(w & 1) + (lane & 15);
            const int s0   = 8*(w >> 1);
            uint32_t kbh[2][4], kbl[2][4];
            #pragma unroll
            for (int g = 0; g < 2; g++) {
                uint32_t off = SWZ((s0 + (lane & 7))*128 + (g*32 + (lane >> 3)*8)*2);
                ldm4(kbh[g], sb + G_KH + off);
                ldm4(kbl[g], sb + G_KL + off);
            }
            float dA[4] = {0,0,0,0};
            #pragma unroll
            for (int ks = 0; ks < 4; ks++) {
                uint32_t ah[4], al[4];
                uint32_t aoff = SWZ(mrow*128 + (ks*16 + (lane >> 4)*8)*2);
                ldm4(ah, sb + G_QH + aoff);
                ldm4(al, sb + G_QL + aoff);
                uint32_t b0h = kbh[ks>>1][(ks&1)*2], b1h = kbh[ks>>1][(ks&1)*2+1];
                uint32_t b0l = kbl[ks>>1][(ks&1)*2], b1l = kbl[ks>>1][(ks&1)*2+1];
                mma16816(dA, ah, b0h, b1h);
                mma16816(dA, ah, b0l, b1l);
                mma16816(dA, al, b0h, b1h);
            }
            int r0 = 16*(w & 1) + (lane >> 2);
            int cc = s0 + 2*(lane & 3);
            float v00 = (cc   <= r0  ) ? dA[0] : 0.f;
            float v01 = (cc+1 <= r0  ) ? dA[1] : 0.f;
            float v10 = (cc   <= r0+8) ? dA[2] : 0.f;
            float v11 = (cc+1 <= r0+8) ? dA[3] : 0.f;
            uint32_t hp, lp;
            bsplit2(v00, v01, hp, lp);
            *reinterpret_cast<uint32_t*>(smem + G_AH + SWZ(r0*128 + cc*2)) = hp;
            *reinterpret_cast<uint32_t*>(smem + G_AL + SWZ(r0*128 + cc*2)) = lp;
            bsplit2(v10, v11, hp, lp);
            *reinterpret_cast<uint32_t*>(smem + G_AH + SWZ((r0+8)*128 + cc*2)) = hp;
            *reinterpret_cast<uint32_t*>(smem + G_AL + SWZ((r0+8)*128 + cc*2)) = lp;
        }
        __syncthreads();
        // o = A@V + Q@S(old) -> U
        {
            const int mrow = 16*(w & 1) + (lane & 15);
            const int nv0  = 16*(w >> 1);
            float d0[4] = {0,0,0,0}, d1[4] = {0,0,0,0};
            #pragma unroll
            for (int ks = 0; ks < 2; ks++) {
                uint32_t ah[4], al[4], vh[4], vl[4];
                uint32_t aoff = SWZ(mrow*128 + (ks*16 + (lane >> 4)*8)*2);
                ldm4(ah, sb + G_AH + aoff);
                ldm4(al, sb + G_AL + aoff);
                uint32_t boff = SWZ((ks*16 + ((lane >> 3) & 1)*8 + (lane & 7))*128
                                    + (nv0 + (lane >> 4)*8)*2);
                ldm4t(vh, sb + G_VH + boff);
                ldm4t(vl, sb + G_VL + boff);
                mma16816(d0, ah, vh[0], vh[1]);
                mma16816(d0, ah, vl[0], vl[1]);
                mma16816(d0, al, vh[0], vh[1]);
                mma16816(d1, ah, vh[2], vh[3]);
                mma16816(d1, ah, vl[2], vl[3]);
                mma16816(d1, al, vh[2], vh[3]);
            }
            #pragma unroll
            for (int ks = 0; ks < 4; ks++) {
                uint32_t qh[4], ql[4], sh[4], sl[4];
                uint32_t aoff = SWZ(mrow*128 + (ks*16 + (lane >> 4)*8)*2);
                ldm4(qh, sb + G_QH + aoff);
                ldm4(ql, sb + G_QL + aoff);
                uint32_t boff = SWZ((ks*16 + ((lane >> 3) & 1)*8 + (lane & 7))*128
                                    + (nv0 + (lane >> 4)*8)*2);
                ldm4t(sh, sb + G_SH + boff);
                ldm4t(sl, sb + G_SL + boff);
                mma16816(d0, qh, sh[0], sh[1]);
                mma16816(d0, qh, sl[0], sl[1]);
                mma16816(d0, ql, sh[0], sh[1]);
                mma16816(d1, qh, sh[2], sh[3]);
                mma16816(d1, qh, sl[2], sl[3]);
                mma16816(d1, ql, sh[2], sh[3]);
            }
            int r0 = 16*(w & 1) + (lane >> 2);
            int c0 = nv0 + 2*(lane & 3);
            *reinterpret_cast<float2*>(&Uf[r0*68 + c0])         = make_float2(d0[0], d0[1]);
            *reinterpret_cast<float2*>(&Uf[(r0+8)*68 + c0])     = make_float2(d0[2], d0[3]);
            *reinterpret_cast<float2*>(&Uf[r0*68 + c0 + 8])     = make_float2(d1[0], d1[1]);
            *reinterpret_cast<float2*>(&Uf[(r0+8)*68 + c0 + 8]) = make_float2(d1[2], d1[3]);
        }
        __syncthreads();
        // gate epilogue -> og hi/lo
        {
            int t = tid >> 3, dv0 = (tid & 7) * 8;
            float4 oa = *reinterpret_cast<const float4*>(&Uf[t*68 + dv0]);
            float4 obv = *reinterpret_cast<const float4*>(&Uf[t*68 + dv0 + 4]);
            float o8[8] = {oa.x,oa.y,oa.z,oa.w,obv.x,obv.y,obv.z,obv.w};
            float ss = 0.f;
            #pragma unroll
            for (int j = 0; j < 8; j++) ss += o8[j]*o8[j];
            ss += __shfl_xor_sync(0xFFFFFFFFu, ss, 4, 8);
            ss += __shfl_xor_sync(0xFFFFFFFFu, ss, 2, 8);
            ss += __shfl_xor_sync(0xFFFFFFFFu, ss, 1, 8);
            float inv = rsqrtf(ss * (1.f/64.f) + 1e-5f);
            int l = lbase + t;
            if (l < L) {
                size_t rb = ((size_t)(n*L + l))*1024 + 768 + h*64 + dv0;
                float4 r0 = *reinterpret_cast<const float4*>(&qkvr[rb]);
                float4 r1 = *reinterpret_cast<const float4*>(&qkvr[rb + 4]);
                float4 g0 = *reinterpret_cast<const float4*>(&gnp[h*64 + dv0]);
                float4 g1 = *reinterpret_cast<const float4*>(&gnp[h*64 + dv0 + 4]);
                float rr[8] = {r0.x,r0.y,r0.z,r0.w,r1.x,r1.y,r1.z,r1.w};
                float gg[8] = {g0.x,g0.y,g0.z,g0.w,g1.x,g1.y,g1.z,g1.w};
                float res[8];
                #pragma unroll
                for (int j = 0; j < 8; j++)
                    res[j] = o8[j] * inv * gg[j] * (rr[j] / (1.f + __expf(-rr[j])));
                uint32_t hq[4], lq[4];
                #pragma unroll
                for (int j = 0; j < 4; j++) bsplit2(res[2*j], res[2*j+1], hq[j], lq[j]);
                size_t tok = order ? ((size_t)l*Nseq + n) : ((size_t)n*L + l);
                size_t o = (tok*256 + h*64 + dv0) >> 1;
                *reinterpret_cast<uint4*>(reinterpret_cast<uint32_t*>(ogh) + o)
                    = make_uint4(hq[0], hq[1], hq[2], hq[3]);
                *reinterpret_cast<uint4*>(reinterpret_cast<uint32_t*>(ogl) + o)
                    = make_uint4(lq[0], lq[1], lq[2], lq[3]);
            }
        }
        // S update (register master)
        {
            const int mk0 = 16*(w & 3);
            const int nb  = 32*(w >> 2);
            float dd[4][4];
            #pragma unroll
            for (int i = 0; i < 4; i++)
                #pragma unroll
                for (int j = 0; j < 4; j++) dd[i][j] = 0.f;
            #pragma unroll
            for (int ks = 0; ks < 2; ks++) {
                uint32_t kh[4], kl[4];
                uint32_t aoff = SWZ((ks*16 + ((lane >> 3) >> 1)*8 + (lane & 7))*128
                                    + (mk0 + ((lane >> 3) & 1)*8)*2);
                ldm4t(kh, sb + G_KH + aoff);
                ldm4t(kl, sb + G_KL + aoff);
                #pragma unroll
                for (int np = 0; np < 2; np++) {
                    uint32_t vh[4], vl[4];
                    uint32_t boff = SWZ((ks*16 + ((lane >> 3) & 1)*8 + (lane & 7))*128
                                        + (nb + 16*np + (lane >> 4)*8)*2);
                    ldm4t(vh, sb + G_VH + boff);
                    ldm4t(vl, sb + G_VL + boff);
                    mma16816(dd[np*2],   kh, vh[0], vh[1]);
                    mma16816(dd[np*2],   kh, vl[0], vl[1]);
                    mma16816(dd[np*2],   kl, vh[0], vh[1]);
                    mma16816(dd[np*2+1], kh, vh[2], vh[3]);
                    mma16816(dd[np*2+1], kh, vl[2], vl[3]);
                    mma16816(dd[np*2+1], kl, vh[2], vh[3]);
                }
            }
            int r0 = mk0 + (lane >> 2);
            float e0 = __expf(glf[r0]);
            float e1 = __expf(glf[r0 + 8]);
            #pragma unroll
            for (int tile = 0; tile < 4; tile++) {
                int cc = nb + ((tile >> 1) * 16) + ((tile & 1) * 8) + 2*(lane & 3);
                float s00 = e0*(sreg[tile][0] + dd[tile][0]);
                float s01 = e0*(sreg[tile][1] + dd[tile][1]);
                float s10 = e1*(sreg[tile][2] + dd[tile][2]);
                float s11 = e1*(sreg[tile][3] + dd[tile][3]);
                sreg[tile][0] = s00; sreg[tile][1] = s01;
                sreg[tile][2] = s10; sreg[tile][3] = s11;
                uint32_t hp, lp;
                bsplit2(s00, s01, hp, lp);
                *reinterpret_cast<uint32_t*>(smem + G_SH + SWZ(r0*128 + cc*2)) = hp;
                *reinterpret_cast<uint32_t*>(smem + G_SL + SWZ(r0*128 + cc*2)) = lp;
                bsplit2(s10, s11, hp, lp);
                *reinterpret_cast<uint32_t*>(smem + G_SH + SWZ((r0+8)*128 + cc*2)) = hp;
                *reinterpret_cast<uint32_t*>(smem + G_SL + SWZ((r0+8)*128 + cc*2)) = lp;
            }
        }
        __syncthreads();
    }
}

// ---------------------------------------------------------------------------
// combine kernels (validated R12)
// ---------------------------------------------------------------------------
__global__ void __launch_bounds__(256)
combine0_kernel(const float* __restrict__ d01, const float* __restrict__ ctb,
                const float* __restrict__ resid, float* __restrict__ out)
{
    extern __shared__ float sm[];
    const int tid = threadIdx.x;
    const int n = blockIdx.x;
    const int b = n >> 8, t = n & 255;
    for (int i = tid; i < 127*128; i += 256) {
        int tok = i >> 7, col = i & 127;
        sm[tok*129 + col] = d01[((size_t)n*127 + tok)*128 + col];
    }
    __syncthreads();
    #pragma unroll 4
    for (int i = tid; i < 8192; i += 256) {
        int q = i & 127, c = i >> 7;
        size_t oidx = (((size_t)b*64 + c)*256 + t)*128 + q;
        float acc = resid[oidx] + ctb[c];
        if (q < 127) acc += sm[q*129 + 2*c];
        if (q >= 1)  acc += sm[(q-1)*129 + 2*c + 1];
        out[oidx] = acc;
    }
}

__global__ void combine1_kernel(const float* __restrict__ d01T, const float* __restrict__ ctb,
                                const float* __restrict__ resid, float* __restrict__ out)
{
    int idx = blockIdx.x * blockDim.x + threadIdx.x;
    if (idx >= ELEMS) return;
    int q = idx & 127, t = (idx >> 7) & 255, c = (idx >> 15) & 63, b = idx >> 21;
    float acc = resid[idx] + ctb[c];
    int mcur = t*512 + b*128 + q;
    if (t < 255) acc += d01T[(size_t)(2*c)*MAXTOK + mcur];
    if (t >= 1)  acc += d01T[(size_t)(2*c + 1)*MAXTOK + mcur - 512];
    out[idx] = acc;
}

struct WPtrs {
    __nv_bfloat16 *wch, *wcl, *wfT_h, *wfT_l, *fh, *fl, *ogh, *ogl;
};
constexpr int HSM2  = 131072;
constexpr int LN1SM = 9*64*33*4;
constexpr int C0SM  = 127*129*4;

static void run_pass(const float* input, const float* gamma, const float* beta,
                     const float* Wq, const float* Wk, const float* Wv,
                     const float* Wg1, const float* Wg2, const float* Wr,
                     const float* gn, const float* Wo,
                     const float* ctw, const float* ctb,
                     const float* resid, float* out,
                     float* A, const WPtrs& W, int pass)
{
    const int N   = pass == 0 ? 1024 : 512;
    const int L   = pass == 0 ? 127  : 255;
    const int nc  = pass == 0 ? 4    : 8;
    const int tok = N * L;
    const int Mt  = tok / 128;

    float* qkvr = A + OF_QKVR;
    float* gk   = A + OF_GK;
    float* d01  = A + OF_D01;

    prep_kernel<<<768, 256>>>(Wq, Wk, Wv, Wr, Wg1, Wg2, Wo, ctw,
                              W.wch, W.wcl, W.wfT_h, W.wfT_l);
    if (pass == 0) lnf0_kernel<<<1024, 128>>>(input, gamma, beta, W.fh, W.fl);
    else           lnf1_kernel<<<512, 256, LN1SM>>>(input, gamma, beta, W.fh, W.fl);
    hg2c<<<dim3(20, Mt), 256, HSMC>>>(W.fh, W.fl, W.wch, W.wcl, qkvr, gk, tok);
    gla_kernel<<<N*4, 256, GSM>>>(qkvr, gk, gn, W.ogh, W.ogl, L, nc, pass, N);
    hg2<<<dim3(Mt, 1), 256, HSM2>>>(W.ogh, W.ogl, W.wfT_h, W.wfT_l, d01, tok, 128, 256, pass);
    if (pass == 0) combine0_kernel<<<1024, 256, C0SM>>>(d01, ctb, resid, out);
    else           combine1_kernel<<<CDIV(ELEMS, 256), 256>>>(d01, ctb, resid, out);
}

extern "C" void kernel_launch(void* const* d_in, const int* in_sizes, int n_in,
                              void* d_out, int out_size)
{
    const float* x = (const float*)d_in[0];
    auto P = [&](int i) { return (const float*)d_in[i]; };

    float* arena = nullptr;
    cudaGetSymbolAddress((void**)&arena, g_arena);
    float* y4 = arena + OF_Y4;

    WPtrs W;
    cudaGetSymbolAddress((void**)&W.wch,   g_wcat_h);
    cudaGetSymbolAddress((void**)&W.wcl,   g_wcat_l);
    cudaGetSymbolAddress((void**)&W.wfT_h, g_wfT_h);
    cudaGetSymbolAddress((void**)&W.wfT_l, g_wfT_l);
    cudaGetSymbolAddress((void**)&W.fh,    g_fh);
    cudaGetSymbolAddress((void**)&W.fl,    g_fl);
    cudaGetSymbolAddress((void**)&W.ogh,   g_ogh);
    cudaGetSymbolAddress((void**)&W.ogl,   g_ogl);

    cudaFuncSetAttribute(hg2c, cudaFuncAttributeMaxDynamicSharedMemorySize, HSMC);
    cudaFuncSetAttribute(hg2,  cudaFuncAttributeMaxDynamicSharedMemorySize, HSM2);
    cudaFuncSetAttribute(gla_kernel,  cudaFuncAttributeMaxDynamicSharedMemorySize, GSM);
    cudaFuncSetAttribute(lnf1_kernel, cudaFuncAttributeMaxDynamicSharedMemorySize, LN1SM);
    cudaFuncSetAttribute(combine0_kernel, cudaFuncAttributeMaxDynamicSharedMemorySize, C0SM);

    run_pass(x, P(2), P(3), P(4), P(5), P(6), P(7), P(8), P(9), P(10), P(11), P(12), P(13),
             x, y4, arena, W, 0);
    run_pass(y4, P(14), P(15), P(16), P(17), P(18), P(19), P(20), P(21), P(22), P(23), P(24), P(25),
             y4, (float*)d_out, arena, W, 1);
}